// round 1
// baseline (speedup 1.0000x reference)
#include <cuda_runtime.h>
#include <math.h>

// Problem constants
#define BATCH 4
#define SEQ   2048
#define DIM   768
#define NHEAD 12
#define HD    64           // head dim
#define NA    64           // a entries per row/head (F)
#define NB    32           // b entries per row/head (MAX_SEQ/F)
#define MROWS (BATCH*SEQ)  // 8192

// Scratch (static device memory — no allocations allowed)
__device__ float g_AY[MROWS * (NHEAD*NA)];      // 8192 x 768
__device__ float g_BY[MROWS * (NHEAD*NB)];      // 8192 x 384
__device__ float g_VY[MROWS * DIM];             // 8192 x 768
__device__ float g_VBAR[BATCH*NHEAD*NA*HD];     // 4*12*64*64
__device__ float g_CTX[MROWS * DIM];            // 8192 x 768

// ---------------------------------------------------------------------------
// Classic 128x128x8 fp32 GEMM, 256 threads, 8x8 register tile per thread.
// C[M,N] = A[M,K] @ B[K,N] (+ bias[N] if bias != nullptr)
// Requires: M%128==0, N%128==0, K%8==0, all pointers 16B aligned, N%4==0.
// ---------------------------------------------------------------------------
__global__ __launch_bounds__(256) void sgemm128(
    const float* __restrict__ A, const float* __restrict__ B,
    float* __restrict__ C, const float* __restrict__ bias,
    int M, int N, int K)
{
    __shared__ __align__(16) float As[8][128];
    __shared__ __align__(16) float Bs[8][128];

    const int tid = threadIdx.x;
    const int tx = tid & 15;        // 0..15 -> col group
    const int ty = tid >> 4;        // 0..15 -> row group
    const int row0 = blockIdx.y * 128;
    const int col0 = blockIdx.x * 128;

    // A tile loader: thread -> (row ra, 4 cols at ca)
    const int ra = tid >> 1;             // 0..127
    const int ca = (tid & 1) * 4;        // 0 or 4
    const float* Aptr = A + (size_t)(row0 + ra) * K + ca;
    // B tile loader: thread -> (row rb, 4 cols at cb)
    const int rb = tid >> 5;             // 0..7
    const int cb = (tid & 31) * 4;       // 0..124
    const float* Bptr = B + (size_t)rb * N + col0 + cb;

    float acc[8][8];
    #pragma unroll
    for (int i = 0; i < 8; i++)
        #pragma unroll
        for (int j = 0; j < 8; j++) acc[i][j] = 0.f;

    for (int k0 = 0; k0 < K; k0 += 8) {
        float4 av = *(const float4*)(Aptr + k0);
        float4 bv = *(const float4*)(Bptr + (size_t)k0 * N);
        As[ca + 0][ra] = av.x;
        As[ca + 1][ra] = av.y;
        As[ca + 2][ra] = av.z;
        As[ca + 3][ra] = av.w;
        *(float4*)&Bs[rb][cb] = bv;
        __syncthreads();

        #pragma unroll
        for (int kk = 0; kk < 8; kk++) {
            float4 a0 = *(const float4*)&As[kk][ty * 8];
            float4 a1 = *(const float4*)&As[kk][ty * 8 + 4];
            float4 b0 = *(const float4*)&Bs[kk][tx * 8];
            float4 b1 = *(const float4*)&Bs[kk][tx * 8 + 4];
            float ar[8] = {a0.x, a0.y, a0.z, a0.w, a1.x, a1.y, a1.z, a1.w};
            float br[8] = {b0.x, b0.y, b0.z, b0.w, b1.x, b1.y, b1.z, b1.w};
            #pragma unroll
            for (int i = 0; i < 8; i++)
                #pragma unroll
                for (int j = 0; j < 8; j++)
                    acc[i][j] = fmaf(ar[i], br[j], acc[i][j]);
        }
        __syncthreads();
    }

    // Epilogue
    float bsum[8];
    #pragma unroll
    for (int j = 0; j < 8; j++)
        bsum[j] = bias ? bias[col0 + tx * 8 + j] : 0.f;

    #pragma unroll
    for (int i = 0; i < 8; i++) {
        const int r = row0 + ty * 8 + i;
        float4 o0 = make_float4(acc[i][0] + bsum[0], acc[i][1] + bsum[1],
                                acc[i][2] + bsum[2], acc[i][3] + bsum[3]);
        float4 o1 = make_float4(acc[i][4] + bsum[4], acc[i][5] + bsum[5],
                                acc[i][6] + bsum[6], acc[i][7] + bsum[7]);
        *(float4*)&C[(size_t)r * N + col0 + tx * 8] = o0;
        *(float4*)&C[(size_t)r * N + col0 + tx * 8 + 4] = o1;
    }
}

// ---------------------------------------------------------------------------
// Pool V over runs of 32 rows: VBAR[b,h,k,d] = sum_{r<32} VY[b*SEQ+32k+r, h*64+d]
// grid: BATCH*NHEAD*NA blocks, 64 threads (d)
// ---------------------------------------------------------------------------
__global__ void pool_v_kernel(const float* __restrict__ VY, float* __restrict__ VBAR)
{
    const int idx = blockIdx.x;
    const int k  = idx & 63;
    const int bh = idx >> 6;             // b*NHEAD + h
    const int h  = bh % NHEAD;
    const int b  = bh / NHEAD;
    const int d  = threadIdx.x;

    const float* base = VY + ((size_t)(b * SEQ + k * 32)) * DIM + h * HD + d;
    float s = 0.f;
    #pragma unroll
    for (int r = 0; r < 32; r++) s += base[(size_t)r * DIM];
    VBAR[((size_t)bh * NA + k) * HD + d] = s;
}

// ---------------------------------------------------------------------------
// Fused softmax(64) + P @ VBAR(64x64) per query row.
// grid: BATCH*NHEAD*(SEQ/256) blocks, 256 threads; 1 thread = 1 query row.
// CTX[b*SEQ+i, h*64+d] = sum_k e_k * VBAR[k,d] / (32 * sum_k e_k)
// ---------------------------------------------------------------------------
__global__ __launch_bounds__(256) void attn_kernel(
    const float* __restrict__ AY, const float* __restrict__ BY,
    const float* __restrict__ VBAR, float* __restrict__ CTX)
{
    __shared__ __align__(16) float Vs[NA][HD];   // 16 KB

    const int bid  = blockIdx.x;
    const int tile = bid & 7;        // SEQ/256 = 8 tiles
    const int bh   = bid >> 3;
    const int h    = bh % NHEAD;
    const int b    = bh / NHEAD;

    // cooperative load of pooled V
    const float* vb = VBAR + (size_t)bh * (NA * HD);
    for (int t = threadIdx.x * 4; t < NA * HD; t += 256 * 4)
        *(float4*)&Vs[0][t] = *(const float4*)&vb[t];
    __syncthreads();

    const int i   = tile * 256 + threadIdx.x;
    const int row = b * SEQ + i;
    const float* arow = AY + (size_t)row * (NHEAD * NA) + h * NA;
    const float* brow = BY + (size_t)row * (NHEAD * NB) + h * NB;

    float e[NA];
    #pragma unroll
    for (int k = 0; k < NA; k += 4) {
        float4 v = *(const float4*)&arow[k];
        e[k] = v.x; e[k + 1] = v.y; e[k + 2] = v.z; e[k + 3] = v.w;
    }
    float bb[NB];
    #pragma unroll
    for (int j = 0; j < NB; j += 4) {
        float4 v = *(const float4*)&brow[j];
        bb[j] = v.x; bb[j + 1] = v.y; bb[j + 2] = v.z; bb[j + 3] = v.w;
    }

    float m = -1e30f;
    #pragma unroll
    for (int k = 0; k < NA; k++) {
        e[k] = e[k] * bb[k >> 1];
        m = fmaxf(m, e[k]);
    }
    float s = 0.f;
    #pragma unroll
    for (int k = 0; k < NA; k++) {
        e[k] = __expf(e[k] - m);
        s += e[k];
    }
    const float inv = 1.f / (32.f * s);

    float out[HD];
    #pragma unroll
    for (int d = 0; d < HD; d++) out[d] = 0.f;

    for (int k = 0; k < NA; k++) {
        const float ek = e[k];
        #pragma unroll
        for (int d = 0; d < HD; d += 4) {
            float4 v = *(const float4*)&Vs[k][d];
            out[d + 0] = fmaf(ek, v.x, out[d + 0]);
            out[d + 1] = fmaf(ek, v.y, out[d + 1]);
            out[d + 2] = fmaf(ek, v.z, out[d + 2]);
            out[d + 3] = fmaf(ek, v.w, out[d + 3]);
        }
    }

    float* crow = CTX + (size_t)row * DIM + h * HD;
    #pragma unroll
    for (int d = 0; d < HD; d += 4) {
        float4 o = make_float4(out[d] * inv, out[d + 1] * inv,
                               out[d + 2] * inv, out[d + 3] * inv);
        *(float4*)&crow[d] = o;
    }
}

// ---------------------------------------------------------------------------
// Launch
// ---------------------------------------------------------------------------
extern "C" void kernel_launch(void* const* d_in, const int* in_sizes, int n_in,
                              void* d_out, int out_size)
{
    const float* x  = (const float*)d_in[0];  // (4,2048,768)
    const float* Wa = (const float*)d_in[1];  // (768,768)
    const float* Wb = (const float*)d_in[2];  // (768,384)
    const float* Wv = (const float*)d_in[3];  // (768,768)
    const float* Wp = (const float*)d_in[4];  // (768,768)
    const float* bp = (const float*)d_in[5];  // (768,)
    float* out = (float*)d_out;               // (4,2048,768)

    float *ay, *by, *vy, *vbar, *ctx;
    cudaGetSymbolAddress((void**)&ay,   g_AY);
    cudaGetSymbolAddress((void**)&by,   g_BY);
    cudaGetSymbolAddress((void**)&vy,   g_VY);
    cudaGetSymbolAddress((void**)&vbar, g_VBAR);
    cudaGetSymbolAddress((void**)&ctx,  g_CTX);

    // Input projections: x @ Wa / Wb / Wv
    sgemm128<<<dim3(DIM / 128, MROWS / 128), 256>>>(x, Wa, ay, nullptr, MROWS, NHEAD * NA, DIM);
    sgemm128<<<dim3((NHEAD * NB) / 128, MROWS / 128), 256>>>(x, Wb, by, nullptr, MROWS, NHEAD * NB, DIM);
    sgemm128<<<dim3(DIM / 128, MROWS / 128), 256>>>(x, Wv, vy, nullptr, MROWS, DIM, DIM);

    // Pool V over 32-row runs
    pool_v_kernel<<<BATCH * NHEAD * NA, HD>>>(vy, vbar);

    // Fused softmax + P@Vbar
    attn_kernel<<<BATCH * NHEAD * (SEQ / 256), 256>>>(ay, by, vbar, ctx);

    // Output projection with bias
    sgemm128<<<dim3(DIM / 128, MROWS / 128), 256>>>(ctx, Wp, out, bp, MROWS, DIM, DIM);
}

// round 3
// speedup vs baseline: 1.9464x; 1.9464x over previous
#include <cuda_runtime.h>
#include <cuda_bf16.h>
#include <stdint.h>
#include <math.h>

// ---------------------------------------------------------------------------
// Problem constants
// ---------------------------------------------------------------------------
#define BATCH 4
#define SEQ   2048
#define DIM   768
#define NHEAD 12
#define HD    64
#define NA    64
#define NB    32
#define MROWS 8192
#define KD    768
#define NAB   1152

// ---------------------------------------------------------------------------
// Static scratch
// ---------------------------------------------------------------------------
__device__ float g_AB[MROWS * NAB];
__device__ float g_VY[MROWS * DIM];
__device__ float g_VBAR[BATCH * NHEAD * NA * HD];
__device__ float g_CTX[MROWS * DIM];
__device__ __align__(256) __nv_bfloat16 g_Xhi[MROWS * KD];
__device__ __align__(256) __nv_bfloat16 g_Xlo[MROWS * KD];
__device__ __align__(256) __nv_bfloat16 g_Chi[MROWS * KD];
__device__ __align__(256) __nv_bfloat16 g_Clo[MROWS * KD];
__device__ __align__(256) __nv_bfloat16 g_Wab_hi[NAB * KD];
__device__ __align__(256) __nv_bfloat16 g_Wab_lo[NAB * KD];
__device__ __align__(256) __nv_bfloat16 g_Wv_hi[DIM * KD];
__device__ __align__(256) __nv_bfloat16 g_Wv_lo[DIM * KD];
__device__ __align__(256) __nv_bfloat16 g_Wp_hi[DIM * KD];
__device__ __align__(256) __nv_bfloat16 g_Wp_lo[DIM * KD];

// ---------------------------------------------------------------------------
// PTX helpers (all compute_80-portable: cp.async / ldmatrix / mma.sync)
// ---------------------------------------------------------------------------
__device__ __forceinline__ uint32_t smem_u32(const void* p) {
    uint32_t a;
    asm("{ .reg .u64 t; cvta.to.shared.u64 t, %1; cvt.u32.u64 %0, t; }"
        : "=r"(a) : "l"(p));
    return a;
}

#define CP16(saddr, gptr) \
    asm volatile("cp.async.cg.shared.global [%0], [%1], 16;" \
                 :: "r"(saddr), "l"(gptr) : "memory")
#define CP_COMMIT() asm volatile("cp.async.commit_group;" ::: "memory")
#define CP_WAIT2()  asm volatile("cp.async.wait_group 2;" ::: "memory")

#define LDM4(r, addr) \
    asm volatile("ldmatrix.sync.aligned.m8n8.x4.shared.b16 {%0,%1,%2,%3}, [%4];" \
                 : "=r"((r)[0]), "=r"((r)[1]), "=r"((r)[2]), "=r"((r)[3]) \
                 : "r"(addr))

#define MMA(c, a, b0, b1) \
    asm volatile("mma.sync.aligned.m16n8k16.row.col.f32.bf16.bf16.f32 " \
                 "{%0,%1,%2,%3}, {%4,%5,%6,%7}, {%8,%9}, {%0,%1,%2,%3};" \
                 : "+f"((c)[0]), "+f"((c)[1]), "+f"((c)[2]), "+f"((c)[3]) \
                 : "r"((a)[0]), "r"((a)[1]), "r"((a)[2]), "r"((a)[3]), \
                   "r"(b0), "r"(b1))

__device__ __forceinline__ void bf16_split(float v, __nv_bfloat16& h, __nv_bfloat16& l) {
    h = __float2bfloat16_rn(v);
    l = __float2bfloat16_rn(v - __bfloat162float(h));
}

// ---------------------------------------------------------------------------
// Weight prep: W[K x N] fp32 row-major -> Thi/Tlo bf16 [N x K]
// ---------------------------------------------------------------------------
__global__ void transpose_split(const float* __restrict__ W, int N,
                                __nv_bfloat16* __restrict__ Thi,
                                __nv_bfloat16* __restrict__ Tlo, int rowoff)
{
    __shared__ float tile[32][33];
    const int n0 = blockIdx.x * 32, k0 = blockIdx.y * 32;
    const int tx = threadIdx.x, ty = threadIdx.y;
    #pragma unroll
    for (int i = 0; i < 32; i += 8)
        tile[ty + i][tx] = W[(size_t)(k0 + ty + i) * N + n0 + tx];
    __syncthreads();
    #pragma unroll
    for (int i = 0; i < 32; i += 8) {
        float v = tile[tx][ty + i];
        __nv_bfloat16 h, l;
        bf16_split(v, h, l);
        size_t o = (size_t)(rowoff + n0 + ty + i) * KD + k0 + tx;
        Thi[o] = h;
        Tlo[o] = l;
    }
}

// ---------------------------------------------------------------------------
// Row split: X fp32 [M x K] -> Xhi/Xlo bf16
// ---------------------------------------------------------------------------
__global__ __launch_bounds__(256) void split_rows(
    const float* __restrict__ X, __nv_bfloat16* __restrict__ Xh,
    __nv_bfloat16* __restrict__ Xl)
{
    const int i = (blockIdx.x * 256 + threadIdx.x) * 4;
    float4 v = *(const float4*)(X + i);
    __nv_bfloat16 h0, h1, h2, h3, l0, l1, l2, l3;
    bf16_split(v.x, h0, l0);
    bf16_split(v.y, h1, l1);
    bf16_split(v.z, h2, l2);
    bf16_split(v.w, h3, l3);
    *(__nv_bfloat162*)(Xh + i)     = __nv_bfloat162(h0, h1);
    *(__nv_bfloat162*)(Xh + i + 2) = __nv_bfloat162(h2, h3);
    *(__nv_bfloat162*)(Xl + i)     = __nv_bfloat162(l0, l1);
    *(__nv_bfloat162*)(Xl + i + 2) = __nv_bfloat162(l2, l3);
}

// ---------------------------------------------------------------------------
// bf16 3-pass split GEMM:  C[M x Ntot] = A @ B^T   (A: [M][K] hi/lo bf16,
// B: [Ntot][K] hi/lo bf16).  CTA tile 128x128, 8 warps (4Mx2N), warp 32x64.
// K-chunk 32, 4-stage cp.async pipeline. Smem rows padded to 80B
// (conflict-free ldmatrix).
// ---------------------------------------------------------------------------
#define KC   32
#define NCH  (KD / KC)      // 24
#define SRB  80             // smem row stride bytes (64 data + 16 pad)
#define BUF  (128 * SRB)    // 10240 B per matrix buffer
#define STG  (4 * BUF)      // Ahi Alo Bhi Blo = 40960 B
#define NSTG 4
#define GSMEM (NSTG * STG)  // 163840 B

__device__ __forceinline__ void ld_chunk(
    uint32_t sb, const __nv_bfloat16* __restrict__ Ah,
    const __nv_bfloat16* __restrict__ Al, const __nv_bfloat16* __restrict__ Bh,
    const __nv_bfloat16* __restrict__ Bl, int row0, int col0, int kc, int tid)
{
    const int r  = tid >> 1;
    const int c0 = (tid & 1) * 2;
    const size_t ga = (size_t)(row0 + r) * KD + kc + c0 * 8;
    const uint32_t sa = sb + r * SRB + c0 * 16;
    CP16(sa,            Ah + ga);
    CP16(sa + 16,       Ah + ga + 8);
    CP16(sa + BUF,      Al + ga);
    CP16(sa + BUF + 16, Al + ga + 8);
    const size_t gb = (size_t)(col0 + r) * KD + kc + c0 * 8;
    const uint32_t sbb = sb + 2 * BUF + r * SRB + c0 * 16;
    CP16(sbb,            Bh + gb);
    CP16(sbb + 16,       Bh + gb + 8);
    CP16(sbb + BUF,      Bl + gb);
    CP16(sbb + BUF + 16, Bl + gb + 8);
}

__global__ void __launch_bounds__(256, 1) gemm_bf16x3(
    const __nv_bfloat16* __restrict__ Ah, const __nv_bfloat16* __restrict__ Al,
    const __nv_bfloat16* __restrict__ Bh, const __nv_bfloat16* __restrict__ Bl,
    float* __restrict__ C, const float* __restrict__ bias, int Cstride)
{
    extern __shared__ char dsm[];
    const uint32_t sbase = smem_u32(dsm);

    const int tid  = threadIdx.x;
    const int wid  = tid >> 5;
    const int lane = tid & 31;
    const int m0 = (wid & 3) * 32;     // warp M offset in tile
    const int n0 = (wid >> 2) * 64;    // warp N offset in tile
    const int row0 = blockIdx.y * 128;
    const int col0 = blockIdx.x * 128;

    float acc[2][8][4];
    #pragma unroll
    for (int i = 0; i < 2; i++)
        #pragma unroll
        for (int j = 0; j < 8; j++)
            #pragma unroll
            for (int q = 0; q < 4; q++) acc[i][j][q] = 0.f;

    // prologue: 3 chunks in flight
    #pragma unroll
    for (int p = 0; p < 3; p++) {
        ld_chunk(sbase + p * STG, Ah, Al, Bh, Bl, row0, col0, p * KC, tid);
        CP_COMMIT();
    }

    const int lr = lane & 15;
    const int lh = lane >> 4;

    #pragma unroll 1
    for (int c = 0; c < NCH; c++) {
        __syncthreads();                       // stage (c+3)&3 free to overwrite
        if (c + 3 < NCH)
            ld_chunk(sbase + ((c + 3) & 3) * STG, Ah, Al, Bh, Bl,
                     row0, col0, (c + 3) * KC, tid);
        CP_COMMIT();
        CP_WAIT2();
        __syncthreads();                       // chunk c visible to all warps

        const uint32_t sb = sbase + (c & 3) * STG;
        #pragma unroll
        for (int kq = 0; kq < 2; kq++) {       // two k16 halves of the 32-chunk
            uint32_t ah[2][4], al[2][4], bh[4][4], bl[4][4];
            #pragma unroll
            for (int mt = 0; mt < 2; mt++) {
                const uint32_t aaddr =
                    sb + (m0 + mt * 16 + lr) * SRB + kq * 32 + lh * 16;
                LDM4(ah[mt], aaddr);
                LDM4(al[mt], aaddr + BUF);
            }
            #pragma unroll
            for (int nt = 0; nt < 4; nt++) {
                const uint32_t baddr =
                    sb + 2 * BUF + (n0 + nt * 16 + lr) * SRB + kq * 32 + lh * 16;
                LDM4(bh[nt], baddr);
                LDM4(bl[nt], baddr + BUF);
            }
            #pragma unroll
            for (int mt = 0; mt < 2; mt++)
                #pragma unroll
                for (int nt = 0; nt < 4; nt++)
                    #pragma unroll
                    for (int h = 0; h < 2; h++) {
                        float* c4 = acc[mt][nt * 2 + h];
                        MMA(c4, ah[mt], bh[nt][h], bh[nt][h + 2]);  // hi*hi
                        MMA(c4, ah[mt], bl[nt][h], bl[nt][h + 2]);  // hi*lo
                        MMA(c4, al[mt], bh[nt][h], bh[nt][h + 2]);  // lo*hi
                    }
        }
    }

    // epilogue
    const int l4 = lane >> 2;
    const int l2 = (lane & 3) * 2;
    #pragma unroll
    for (int mt = 0; mt < 2; mt++) {
        #pragma unroll
        for (int j = 0; j < 8; j++) {
            const int grow = row0 + m0 + mt * 16 + l4;
            const int gcol = col0 + n0 + j * 8 + l2;
            float b0 = 0.f, b1 = 0.f;
            if (bias) { b0 = bias[gcol]; b1 = bias[gcol + 1]; }
            float2 v0 = make_float2(acc[mt][j][0] + b0, acc[mt][j][1] + b1);
            float2 v1 = make_float2(acc[mt][j][2] + b0, acc[mt][j][3] + b1);
            *(float2*)(C + (size_t)grow * Cstride + gcol) = v0;
            *(float2*)(C + (size_t)(grow + 8) * Cstride + gcol) = v1;
        }
    }
}

// ---------------------------------------------------------------------------
// Pool V over runs of 32 rows
// ---------------------------------------------------------------------------
__global__ void pool_v_kernel(const float* __restrict__ VY, float* __restrict__ VBAR)
{
    const int idx = blockIdx.x;
    const int k  = idx & 63;
    const int bh = idx >> 6;
    const int h  = bh % NHEAD;
    const int b  = bh / NHEAD;
    const int d  = threadIdx.x;

    const float* base = VY + ((size_t)(b * SEQ + k * 32)) * DIM + h * HD + d;
    float s = 0.f;
    #pragma unroll
    for (int r = 0; r < 32; r++) s += base[(size_t)r * DIM];
    VBAR[((size_t)bh * NA + k) * HD + d] = s;
}

// ---------------------------------------------------------------------------
// Fused softmax(64) + P @ VBAR(64x64) per query row (reads fused AB buffer)
// ---------------------------------------------------------------------------
__global__ __launch_bounds__(256) void attn_kernel(
    const float* __restrict__ AB, const float* __restrict__ VBAR,
    float* __restrict__ CTX)
{
    __shared__ __align__(16) float Vs[NA][HD];

    const int bid  = blockIdx.x;
    const int tile = bid & 7;
    const int bh   = bid >> 3;
    const int h    = bh % NHEAD;
    const int b    = bh / NHEAD;

    const float* vb = VBAR + (size_t)bh * (NA * HD);
    for (int t = threadIdx.x * 4; t < NA * HD; t += 256 * 4)
        *(float4*)&Vs[0][t] = *(const float4*)&vb[t];
    __syncthreads();

    const int i   = tile * 256 + threadIdx.x;
    const int row = b * SEQ + i;
    const float* arow = AB + (size_t)row * NAB + h * NA;
    const float* brow = AB + (size_t)row * NAB + DIM + h * NB;

    float e[NA];
    #pragma unroll
    for (int k = 0; k < NA; k += 4) {
        float4 v = *(const float4*)&arow[k];
        e[k] = v.x; e[k + 1] = v.y; e[k + 2] = v.z; e[k + 3] = v.w;
    }
    float bb[NB];
    #pragma unroll
    for (int q = 0; q < NB; q += 4) {
        float4 v = *(const float4*)&brow[q];
        bb[q] = v.x; bb[q + 1] = v.y; bb[q + 2] = v.z; bb[q + 3] = v.w;
    }

    float m = -1e30f;
    #pragma unroll
    for (int k = 0; k < NA; k++) {
        e[k] = e[k] * bb[k >> 1];
        m = fmaxf(m, e[k]);
    }
    float s = 0.f;
    #pragma unroll
    for (int k = 0; k < NA; k++) {
        e[k] = __expf(e[k] - m);
        s += e[k];
    }
    const float inv = 1.f / (32.f * s);

    float out[HD];
    #pragma unroll
    for (int d = 0; d < HD; d++) out[d] = 0.f;

    for (int k = 0; k < NA; k++) {
        const float ek = e[k];
        #pragma unroll
        for (int d = 0; d < HD; d += 4) {
            float4 v = *(const float4*)&Vs[k][d];
            out[d + 0] = fmaf(ek, v.x, out[d + 0]);
            out[d + 1] = fmaf(ek, v.y, out[d + 1]);
            out[d + 2] = fmaf(ek, v.z, out[d + 2]);
            out[d + 3] = fmaf(ek, v.w, out[d + 3]);
        }
    }

    float* crow = CTX + (size_t)row * DIM + h * HD;
    #pragma unroll
    for (int d = 0; d < HD; d += 4) {
        float4 o = make_float4(out[d] * inv, out[d + 1] * inv,
                               out[d + 2] * inv, out[d + 3] * inv);
        *(float4*)&crow[d] = o;
    }
}

// ---------------------------------------------------------------------------
// Launch
// ---------------------------------------------------------------------------
extern "C" void kernel_launch(void* const* d_in, const int* in_sizes, int n_in,
                              void* d_out, int out_size)
{
    const float* x  = (const float*)d_in[0];
    const float* Wa = (const float*)d_in[1];
    const float* Wb = (const float*)d_in[2];
    const float* Wv = (const float*)d_in[3];
    const float* Wp = (const float*)d_in[4];
    const float* bp = (const float*)d_in[5];
    float* out = (float*)d_out;

    float *ab, *vy, *vbar, *ctx;
    __nv_bfloat16 *xh, *xl, *ch, *cl;
    __nv_bfloat16 *wab_h, *wab_l, *wv_h, *wv_l, *wp_h, *wp_l;
    cudaGetSymbolAddress((void**)&ab,   g_AB);
    cudaGetSymbolAddress((void**)&vy,   g_VY);
    cudaGetSymbolAddress((void**)&vbar, g_VBAR);
    cudaGetSymbolAddress((void**)&ctx,  g_CTX);
    cudaGetSymbolAddress((void**)&xh,   g_Xhi);
    cudaGetSymbolAddress((void**)&xl,   g_Xlo);
    cudaGetSymbolAddress((void**)&ch,   g_Chi);
    cudaGetSymbolAddress((void**)&cl,   g_Clo);
    cudaGetSymbolAddress((void**)&wab_h, g_Wab_hi);
    cudaGetSymbolAddress((void**)&wab_l, g_Wab_lo);
    cudaGetSymbolAddress((void**)&wv_h,  g_Wv_hi);
    cudaGetSymbolAddress((void**)&wv_l,  g_Wv_lo);
    cudaGetSymbolAddress((void**)&wp_h,  g_Wp_hi);
    cudaGetSymbolAddress((void**)&wp_l,  g_Wp_lo);

    cudaFuncSetAttribute(gemm_bf16x3,
                         cudaFuncAttributeMaxDynamicSharedMemorySize, GSMEM);

    dim3 tb(32, 8);
    transpose_split<<<dim3(DIM / 32, KD / 32), tb>>>(Wa, DIM, wab_h, wab_l, 0);
    transpose_split<<<dim3((NHEAD * NB) / 32, KD / 32), tb>>>(Wb, NHEAD * NB, wab_h, wab_l, DIM);
    transpose_split<<<dim3(DIM / 32, KD / 32), tb>>>(Wv, DIM, wv_h, wv_l, 0);
    transpose_split<<<dim3(DIM / 32, KD / 32), tb>>>(Wp, DIM, wp_h, wp_l, 0);

    split_rows<<<(MROWS * KD) / (256 * 4), 256>>>(x, xh, xl);

    // x @ [Wa|Wb] -> AB (8192 x 1152)
    gemm_bf16x3<<<dim3(NAB / 128, MROWS / 128), 256, GSMEM>>>(
        xh, xl, wab_h, wab_l, ab, nullptr, NAB);
    // x @ Wv -> VY
    gemm_bf16x3<<<dim3(DIM / 128, MROWS / 128), 256, GSMEM>>>(
        xh, xl, wv_h, wv_l, vy, nullptr, DIM);

    pool_v_kernel<<<BATCH * NHEAD * NA, HD>>>(vy, vbar);
    attn_kernel<<<BATCH * NHEAD * (SEQ / 256), 256>>>(ab, vbar, ctx);

    split_rows<<<(MROWS * KD) / (256 * 4), 256>>>(ctx, ch, cl);

    // ctx @ Wp + bp -> out
    gemm_bf16x3<<<dim3(DIM / 128, MROWS / 128), 256, GSMEM>>>(
        ch, cl, wp_h, wp_l, out, bp, DIM);
}

// round 4
// speedup vs baseline: 2.0284x; 1.0421x over previous
#include <cuda_runtime.h>
#include <cuda_bf16.h>
#include <stdint.h>
#include <math.h>

// ---------------------------------------------------------------------------
// Problem constants
// ---------------------------------------------------------------------------
#define BATCH 4
#define SEQ   2048
#define DIM   768
#define NHEAD 12
#define HD    64
#define NA    64
#define NB    32
#define MROWS 8192
#define KD    768
#define NAB   1152
#define NTOT  1920          // fused [Wa|Wb|Wv] output width

// ---------------------------------------------------------------------------
// Static scratch
// ---------------------------------------------------------------------------
__device__ __align__(256) float g_Y[MROWS * NTOT];          // x@[Wa|Wb|Wv]
__device__ float g_VBAR[BATCH * NHEAD * NA * HD];
__device__ __align__(256) __nv_bfloat16 g_Xhi[MROWS * KD];
__device__ __align__(256) __nv_bfloat16 g_Xlo[MROWS * KD];
__device__ __align__(256) __nv_bfloat16 g_Chi[MROWS * KD];
__device__ __align__(256) __nv_bfloat16 g_Clo[MROWS * KD];
__device__ __align__(256) __nv_bfloat16 g_W1_hi[NTOT * KD];
__device__ __align__(256) __nv_bfloat16 g_W1_lo[NTOT * KD];
__device__ __align__(256) __nv_bfloat16 g_Wp_hi[DIM * KD];
__device__ __align__(256) __nv_bfloat16 g_Wp_lo[DIM * KD];

// ---------------------------------------------------------------------------
// PTX helpers (compute_80-portable)
// ---------------------------------------------------------------------------
__device__ __forceinline__ uint32_t smem_u32(const void* p) {
    uint32_t a;
    asm("{ .reg .u64 t; cvta.to.shared.u64 t, %1; cvt.u32.u64 %0, t; }"
        : "=r"(a) : "l"(p));
    return a;
}

#define CP16(saddr, gptr) \
    asm volatile("cp.async.cg.shared.global [%0], [%1], 16;" \
                 :: "r"(saddr), "l"(gptr) : "memory")
#define CP_COMMIT() asm volatile("cp.async.commit_group;" ::: "memory")
#define CP_WAIT1()  asm volatile("cp.async.wait_group 1;" ::: "memory")

#define LDM4(r, addr) \
    asm volatile("ldmatrix.sync.aligned.m8n8.x4.shared.b16 {%0,%1,%2,%3}, [%4];" \
                 : "=r"((r)[0]), "=r"((r)[1]), "=r"((r)[2]), "=r"((r)[3]) \
                 : "r"(addr))

#define MMA(c, a, b0, b1) \
    asm volatile("mma.sync.aligned.m16n8k16.row.col.f32.bf16.bf16.f32 " \
                 "{%0,%1,%2,%3}, {%4,%5,%6,%7}, {%8,%9}, {%0,%1,%2,%3};" \
                 : "+f"((c)[0]), "+f"((c)[1]), "+f"((c)[2]), "+f"((c)[3]) \
                 : "r"((a)[0]), "r"((a)[1]), "r"((a)[2]), "r"((a)[3]), \
                   "r"(b0), "r"(b1))

__device__ __forceinline__ void bf16_split(float v, __nv_bfloat16& h, __nv_bfloat16& l) {
    h = __float2bfloat16_rn(v);
    l = __float2bfloat16_rn(v - __bfloat162float(h));
}

// ---------------------------------------------------------------------------
// Weight prep: W[K x N] fp32 row-major -> Thi/Tlo bf16 [N x K]
// ---------------------------------------------------------------------------
__global__ void transpose_split(const float* __restrict__ W, int N,
                                __nv_bfloat16* __restrict__ Thi,
                                __nv_bfloat16* __restrict__ Tlo, int rowoff)
{
    __shared__ float tile[32][33];
    const int n0 = blockIdx.x * 32, k0 = blockIdx.y * 32;
    const int tx = threadIdx.x, ty = threadIdx.y;
    #pragma unroll
    for (int i = 0; i < 32; i += 8)
        tile[ty + i][tx] = W[(size_t)(k0 + ty + i) * N + n0 + tx];
    __syncthreads();
    #pragma unroll
    for (int i = 0; i < 32; i += 8) {
        float v = tile[tx][ty + i];
        __nv_bfloat16 h, l;
        bf16_split(v, h, l);
        size_t o = (size_t)(rowoff + n0 + ty + i) * KD + k0 + tx;
        Thi[o] = h;
        Tlo[o] = l;
    }
}

// ---------------------------------------------------------------------------
// Row split: X fp32 [M x K] -> Xhi/Xlo bf16
// ---------------------------------------------------------------------------
__global__ __launch_bounds__(256) void split_rows(
    const float* __restrict__ X, __nv_bfloat16* __restrict__ Xh,
    __nv_bfloat16* __restrict__ Xl)
{
    const int i = (blockIdx.x * 256 + threadIdx.x) * 4;
    float4 v = *(const float4*)(X + i);
    __nv_bfloat16 h0, h1, h2, h3, l0, l1, l2, l3;
    bf16_split(v.x, h0, l0);
    bf16_split(v.y, h1, l1);
    bf16_split(v.z, h2, l2);
    bf16_split(v.w, h3, l3);
    *(__nv_bfloat162*)(Xh + i)     = __nv_bfloat162(h0, h1);
    *(__nv_bfloat162*)(Xh + i + 2) = __nv_bfloat162(h2, h3);
    *(__nv_bfloat162*)(Xl + i)     = __nv_bfloat162(l0, l1);
    *(__nv_bfloat162*)(Xl + i + 2) = __nv_bfloat162(l2, l3);
}

// ---------------------------------------------------------------------------
// bf16 3-pass split GEMM: C[M x Ntot] = A @ B^T
// CTA tile 128x128, 8 warps (4Mx2N), warp 32x64.
// K-chunk 64, 3-stage SW128-swizzled smem pipeline, ONE syncthreads/chunk.
// ---------------------------------------------------------------------------
#define KC    64
#define NCH   (KD / KC)       // 12
#define SBUF  16384           // 128 rows x 128 B (one matrix, swizzled)
#define STG   (4 * SBUF)      // Ahi Alo Bhi Blo = 64 KB
#define NSTG  3
#define GSMEM (NSTG * STG)    // 192 KB

#define SWZ(row, ch) (((uint32_t)(row) << 7) + ((((uint32_t)(ch)) ^ ((row) & 7)) << 4))

__device__ __forceinline__ void ld_chunk(
    uint32_t sb, const __nv_bfloat16* __restrict__ Ah,
    const __nv_bfloat16* __restrict__ Al, const __nv_bfloat16* __restrict__ Bh,
    const __nv_bfloat16* __restrict__ Bl, int row0, int col0, int kc, int tid)
{
    const int r    = tid >> 1;        // 0..127
    const int half = tid & 1;         // 0..1  (chunks half*4 .. half*4+3)
    const size_t ga = (size_t)(row0 + r) * KD + kc + half * 32;
    const size_t gb = (size_t)(col0 + r) * KD + kc + half * 32;
    #pragma unroll
    for (int i = 0; i < 4; i++) {
        const uint32_t so = SWZ(r, half * 4 + i);
        CP16(sb + so,            Ah + ga + i * 8);
        CP16(sb + SBUF + so,     Al + ga + i * 8);
        CP16(sb + 2 * SBUF + so, Bh + gb + i * 8);
        CP16(sb + 3 * SBUF + so, Bl + gb + i * 8);
    }
}

__global__ void __launch_bounds__(256, 1) gemm_bf16x3(
    const __nv_bfloat16* __restrict__ Ah, const __nv_bfloat16* __restrict__ Al,
    const __nv_bfloat16* __restrict__ Bh, const __nv_bfloat16* __restrict__ Bl,
    float* __restrict__ C, const float* __restrict__ bias, int Cstride)
{
    extern __shared__ char dsm[];
    const uint32_t sbase = smem_u32(dsm);

    const int tid  = threadIdx.x;
    const int wid  = tid >> 5;
    const int lane = tid & 31;
    const int m0 = (wid & 3) * 32;
    const int n0 = (wid >> 2) * 64;
    const int row0 = blockIdx.y * 128;
    const int col0 = blockIdx.x * 128;
    const int lr = lane & 15;
    const int lh = lane >> 4;
    const int r7 = lr & 7;

    // row-base byte offsets (swizzle col-part added per kq)
    uint32_t aRow[2], bRow[4];
    #pragma unroll
    for (int mt = 0; mt < 2; mt++) aRow[mt] = (uint32_t)(m0 + mt * 16 + lr) << 7;
    #pragma unroll
    for (int nt = 0; nt < 4; nt++) bRow[nt] = (uint32_t)(n0 + nt * 16 + lr) << 7;

    float acc[2][8][4];
    #pragma unroll
    for (int i = 0; i < 2; i++)
        #pragma unroll
        for (int j = 0; j < 8; j++)
            #pragma unroll
            for (int q = 0; q < 4; q++) acc[i][j][q] = 0.f;

    // prologue: chunks 0,1 -> stages 0,1
    ld_chunk(sbase,       Ah, Al, Bh, Bl, row0, col0, 0,  tid);
    CP_COMMIT();
    ld_chunk(sbase + STG, Ah, Al, Bh, Bl, row0, col0, KC, tid);
    CP_COMMIT();

    int stage = 0;
    #pragma unroll 1
    for (int c = 0; c < NCH; c++) {
        CP_WAIT1();            // chunk c resident (own-thread view)
        __syncthreads();       // visible to all; stage (c-1)%3 now free

        if (c + 2 < NCH) {
            int ws = stage + 2; if (ws >= NSTG) ws -= NSTG;
            ld_chunk(sbase + ws * STG, Ah, Al, Bh, Bl,
                     row0, col0, (c + 2) * KC, tid);
        }
        CP_COMMIT();

        const uint32_t sb = sbase + stage * STG;
        #pragma unroll
        for (int kq = 0; kq < 4; kq++) {
            const uint32_t xp = (uint32_t)(((kq * 2 + lh) ^ r7) << 4);
            uint32_t ah[2][4], al[2][4], bh[4][4], bl[4][4];
            #pragma unroll
            for (int mt = 0; mt < 2; mt++) {
                LDM4(ah[mt], sb + aRow[mt] + xp);
                LDM4(al[mt], sb + SBUF + aRow[mt] + xp);
            }
            #pragma unroll
            for (int nt = 0; nt < 4; nt++) {
                LDM4(bh[nt], sb + 2 * SBUF + bRow[nt] + xp);
                LDM4(bl[nt], sb + 3 * SBUF + bRow[nt] + xp);
            }
            // pass 1: hi*hi
            #pragma unroll
            for (int mt = 0; mt < 2; mt++)
                #pragma unroll
                for (int nt = 0; nt < 4; nt++)
                    #pragma unroll
                    for (int h = 0; h < 2; h++)
                        MMA(acc[mt][nt * 2 + h], ah[mt], bh[nt][h], bh[nt][h + 2]);
            // pass 2: hi*lo
            #pragma unroll
            for (int mt = 0; mt < 2; mt++)
                #pragma unroll
                for (int nt = 0; nt < 4; nt++)
                    #pragma unroll
                    for (int h = 0; h < 2; h++)
                        MMA(acc[mt][nt * 2 + h], ah[mt], bl[nt][h], bl[nt][h + 2]);
            // pass 3: lo*hi
            #pragma unroll
            for (int mt = 0; mt < 2; mt++)
                #pragma unroll
                for (int nt = 0; nt < 4; nt++)
                    #pragma unroll
                    for (int h = 0; h < 2; h++)
                        MMA(acc[mt][nt * 2 + h], al[mt], bh[nt][h], bh[nt][h + 2]);
        }
        stage++; if (stage >= NSTG) stage = 0;
    }

    // epilogue
    const int l4 = lane >> 2;
    const int l2 = (lane & 3) * 2;
    #pragma unroll
    for (int mt = 0; mt < 2; mt++) {
        #pragma unroll
        for (int j = 0; j < 8; j++) {
            const int grow = row0 + m0 + mt * 16 + l4;
            const int gcol = col0 + n0 + j * 8 + l2;
            float b0 = 0.f, b1 = 0.f;
            if (bias) { b0 = bias[gcol]; b1 = bias[gcol + 1]; }
            float2 v0 = make_float2(acc[mt][j][0] + b0, acc[mt][j][1] + b1);
            float2 v1 = make_float2(acc[mt][j][2] + b0, acc[mt][j][3] + b1);
            *(float2*)(C + (size_t)grow * Cstride + gcol) = v0;
            *(float2*)(C + (size_t)(grow + 8) * Cstride + gcol) = v1;
        }
    }
}

// ---------------------------------------------------------------------------
// Pool V over runs of 32 rows (VY lives in cols [1152,1920) of Y)
// ---------------------------------------------------------------------------
__global__ void pool_v_kernel(const float* __restrict__ Y, float* __restrict__ VBAR)
{
    const int idx = blockIdx.x;
    const int k  = idx & 63;
    const int bh = idx >> 6;
    const int h  = bh % NHEAD;
    const int b  = bh / NHEAD;
    const int d  = threadIdx.x;

    const float* base = Y + ((size_t)(b * SEQ + k * 32)) * NTOT + NAB + h * HD + d;
    float s = 0.f;
    #pragma unroll
    for (int r = 0; r < 32; r++) s += base[(size_t)r * NTOT];
    VBAR[((size_t)bh * NA + k) * HD + d] = s;
}

// ---------------------------------------------------------------------------
// Fused softmax(64) + P @ VBAR(64x64) per query row; writes bf16 hi/lo ctx.
// ---------------------------------------------------------------------------
__global__ __launch_bounds__(256) void attn_kernel(
    const float* __restrict__ Y, const float* __restrict__ VBAR,
    __nv_bfloat16* __restrict__ Ch, __nv_bfloat16* __restrict__ Cl)
{
    __shared__ __align__(16) float Vs[NA][HD];

    const int bid  = blockIdx.x;
    const int tile = bid & 7;
    const int bh   = bid >> 3;
    const int h    = bh % NHEAD;
    const int b    = bh / NHEAD;

    const float* vb = VBAR + (size_t)bh * (NA * HD);
    for (int t = threadIdx.x * 4; t < NA * HD; t += 256 * 4)
        *(float4*)&Vs[0][t] = *(const float4*)&vb[t];
    __syncthreads();

    const int i   = tile * 256 + threadIdx.x;
    const int row = b * SEQ + i;
    const float* arow = Y + (size_t)row * NTOT + h * NA;
    const float* brow = Y + (size_t)row * NTOT + DIM + h * NB;

    float e[NA];
    #pragma unroll
    for (int k = 0; k < NA; k += 4) {
        float4 v = *(const float4*)&arow[k];
        e[k] = v.x; e[k + 1] = v.y; e[k + 2] = v.z; e[k + 3] = v.w;
    }
    float bb[NB];
    #pragma unroll
    for (int q = 0; q < NB; q += 4) {
        float4 v = *(const float4*)&brow[q];
        bb[q] = v.x; bb[q + 1] = v.y; bb[q + 2] = v.z; bb[q + 3] = v.w;
    }

    float m = -1e30f;
    #pragma unroll
    for (int k = 0; k < NA; k++) {
        e[k] = e[k] * bb[k >> 1];
        m = fmaxf(m, e[k]);
    }
    float s = 0.f;
    #pragma unroll
    for (int k = 0; k < NA; k++) {
        e[k] = __expf(e[k] - m);
        s += e[k];
    }
    const float inv = 1.f / (32.f * s);

    float out[HD];
    #pragma unroll
    for (int d = 0; d < HD; d++) out[d] = 0.f;

    for (int k = 0; k < NA; k++) {
        const float ek = e[k];
        #pragma unroll
        for (int d = 0; d < HD; d += 4) {
            float4 v = *(const float4*)&Vs[k][d];
            out[d + 0] = fmaf(ek, v.x, out[d + 0]);
            out[d + 1] = fmaf(ek, v.y, out[d + 1]);
            out[d + 2] = fmaf(ek, v.z, out[d + 2]);
            out[d + 3] = fmaf(ek, v.w, out[d + 3]);
        }
    }

    const size_t co = (size_t)row * DIM + h * HD;
    #pragma unroll
    for (int d = 0; d < HD; d += 2) {
        float v0 = out[d] * inv, v1 = out[d + 1] * inv;
        __nv_bfloat16 h0, h1, l0, l1;
        bf16_split(v0, h0, l0);
        bf16_split(v1, h1, l1);
        *(__nv_bfloat162*)(Ch + co + d) = __nv_bfloat162(h0, h1);
        *(__nv_bfloat162*)(Cl + co + d) = __nv_bfloat162(l0, l1);
    }
}

// ---------------------------------------------------------------------------
// Launch
// ---------------------------------------------------------------------------
extern "C" void kernel_launch(void* const* d_in, const int* in_sizes, int n_in,
                              void* d_out, int out_size)
{
    const float* x  = (const float*)d_in[0];
    const float* Wa = (const float*)d_in[1];
    const float* Wb = (const float*)d_in[2];
    const float* Wv = (const float*)d_in[3];
    const float* Wp = (const float*)d_in[4];
    const float* bp = (const float*)d_in[5];
    float* out = (float*)d_out;

    float *y, *vbar;
    __nv_bfloat16 *xh, *xl, *ch, *cl, *w1h, *w1l, *wph, *wpl;
    cudaGetSymbolAddress((void**)&y,    g_Y);
    cudaGetSymbolAddress((void**)&vbar, g_VBAR);
    cudaGetSymbolAddress((void**)&xh,   g_Xhi);
    cudaGetSymbolAddress((void**)&xl,   g_Xlo);
    cudaGetSymbolAddress((void**)&ch,   g_Chi);
    cudaGetSymbolAddress((void**)&cl,   g_Clo);
    cudaGetSymbolAddress((void**)&w1h,  g_W1_hi);
    cudaGetSymbolAddress((void**)&w1l,  g_W1_lo);
    cudaGetSymbolAddress((void**)&wph,  g_Wp_hi);
    cudaGetSymbolAddress((void**)&wpl,  g_Wp_lo);

    cudaFuncSetAttribute(gemm_bf16x3,
                         cudaFuncAttributeMaxDynamicSharedMemorySize, GSMEM);

    dim3 tb(32, 8);
    transpose_split<<<dim3(DIM / 32, KD / 32), tb>>>(Wa, DIM, w1h, w1l, 0);
    transpose_split<<<dim3((NHEAD * NB) / 32, KD / 32), tb>>>(Wb, NHEAD * NB, w1h, w1l, DIM);
    transpose_split<<<dim3(DIM / 32, KD / 32), tb>>>(Wv, DIM, w1h, w1l, NAB);
    transpose_split<<<dim3(DIM / 32, KD / 32), tb>>>(Wp, DIM, wph, wpl, 0);

    split_rows<<<(MROWS * KD) / (256 * 4), 256>>>(x, xh, xl);

    // x @ [Wa|Wb|Wv] -> Y (8192 x 1920)
    gemm_bf16x3<<<dim3(NTOT / 128, MROWS / 128), 256, GSMEM>>>(
        xh, xl, w1h, w1l, y, nullptr, NTOT);

    pool_v_kernel<<<BATCH * NHEAD * NA, HD>>>(y, vbar);
    attn_kernel<<<BATCH * NHEAD * (SEQ / 256), 256>>>(y, vbar, ch, cl);

    // ctx @ Wp + bp -> out
    gemm_bf16x3<<<dim3(DIM / 128, MROWS / 128), 256, GSMEM>>>(
        ch, cl, wph, wpl, out, bp, DIM);
}

// round 5
// speedup vs baseline: 4.3036x; 2.1217x over previous
#include <cuda_runtime.h>
#include <cuda_fp16.h>
#include <stdint.h>
#include <math.h>

// ---------------------------------------------------------------------------
// Problem constants
// ---------------------------------------------------------------------------
#define BATCH 4
#define SEQ   2048
#define DIM   768
#define NHEAD 12
#define HD    64
#define NA    64
#define NB    32
#define MROWS 8192
#define KD    768
#define NAB   1152
#define NTOT  1920          // fused [Wa|Wb|Wv] output width

// ---------------------------------------------------------------------------
// Static scratch
// ---------------------------------------------------------------------------
__device__ __align__(256) float g_Y[MROWS * NTOT];          // x@[Wa|Wb|Wv] fp32
__device__ float g_VBAR[BATCH * NHEAD * NA * HD];
__device__ __align__(256) __half g_Xh[MROWS * KD];          // x in fp16
__device__ __align__(256) __half g_Ch[MROWS * KD];          // ctx in fp16
__device__ __align__(256) __half g_W1[NTOT * KD];           // [Wa|Wb|Wv]^T fp16
__device__ __align__(256) __half g_Wp[DIM * KD];            // Wp^T fp16

// ---------------------------------------------------------------------------
// PTX helpers (compute_80-portable)
// ---------------------------------------------------------------------------
__device__ __forceinline__ uint32_t smem_u32(const void* p) {
    uint32_t a;
    asm("{ .reg .u64 t; cvta.to.shared.u64 t, %1; cvt.u32.u64 %0, t; }"
        : "=r"(a) : "l"(p));
    return a;
}

#define CP16(saddr, gptr) \
    asm volatile("cp.async.cg.shared.global [%0], [%1], 16;" \
                 :: "r"(saddr), "l"(gptr) : "memory")
#define CP_COMMIT() asm volatile("cp.async.commit_group;" ::: "memory")
#define CP_WAIT1()  asm volatile("cp.async.wait_group 1;" ::: "memory")

#define LDM4(r, addr) \
    asm volatile("ldmatrix.sync.aligned.m8n8.x4.shared.b16 {%0,%1,%2,%3}, [%4];" \
                 : "=r"((r)[0]), "=r"((r)[1]), "=r"((r)[2]), "=r"((r)[3]) \
                 : "r"(addr))

#define MMA(c, a, b0, b1) \
    asm volatile("mma.sync.aligned.m16n8k16.row.col.f32.f16.f16.f32 " \
                 "{%0,%1,%2,%3}, {%4,%5,%6,%7}, {%8,%9}, {%0,%1,%2,%3};" \
                 : "+f"((c)[0]), "+f"((c)[1]), "+f"((c)[2]), "+f"((c)[3]) \
                 : "r"((a)[0]), "r"((a)[1]), "r"((a)[2]), "r"((a)[3]), \
                   "r"(b0), "r"(b1))

// ---------------------------------------------------------------------------
// Weight prep: W[K x N] fp32 row-major -> T[N x K] fp16
// ---------------------------------------------------------------------------
__global__ void transpose_cvt(const float* __restrict__ W, int N,
                              __half* __restrict__ T, int rowoff)
{
    __shared__ float tile[32][33];
    const int n0 = blockIdx.x * 32, k0 = blockIdx.y * 32;
    const int tx = threadIdx.x, ty = threadIdx.y;
    #pragma unroll
    for (int i = 0; i < 32; i += 8)
        tile[ty + i][tx] = W[(size_t)(k0 + ty + i) * N + n0 + tx];
    __syncthreads();
    #pragma unroll
    for (int i = 0; i < 32; i += 8)
        T[(size_t)(rowoff + n0 + ty + i) * KD + k0 + tx] =
            __float2half_rn(tile[tx][ty + i]);
}

// ---------------------------------------------------------------------------
// fp32 -> fp16 convert (x)
// ---------------------------------------------------------------------------
__global__ __launch_bounds__(256) void cvt_rows(
    const float* __restrict__ X, __half* __restrict__ Xh)
{
    const int i = (blockIdx.x * 256 + threadIdx.x) * 8;
    float4 v0 = *(const float4*)(X + i);
    float4 v1 = *(const float4*)(X + i + 4);
    __half2 h[4];
    h[0] = __floats2half2_rn(v0.x, v0.y);
    h[1] = __floats2half2_rn(v0.z, v0.w);
    h[2] = __floats2half2_rn(v1.x, v1.y);
    h[3] = __floats2half2_rn(v1.z, v1.w);
    *(uint4*)(Xh + i) = *(uint4*)h;
}

// ---------------------------------------------------------------------------
// fp16 single-pass GEMM: C[M x Ntot] = A @ B^T  (A:[M][K], B:[Ntot][K] fp16)
// CTA tile 128x128, 8 warps (4Mx2N), warp 32x64.
// K-chunk 64, 3-stage SW128-swizzled pipeline, 96 KB smem, 2 CTAs/SM.
// ---------------------------------------------------------------------------
#define KC    64
#define NCH   (KD / KC)       // 12
#define SBUF  16384           // 128 rows x 128 B (one matrix, swizzled)
#define STG   (2 * SBUF)      // A + B = 32 KB
#define NSTG  3
#define GSMEM (NSTG * STG)    // 96 KB

#define SWZ(row, ch) (((uint32_t)(row) << 7) + ((((uint32_t)(ch)) ^ ((row) & 7)) << 4))

__device__ __forceinline__ void ld_chunk(
    uint32_t sb, const __half* __restrict__ Ag, const __half* __restrict__ Bg,
    int row0, int col0, int kc, int tid)
{
    const int r    = tid >> 1;        // 0..127
    const int half = tid & 1;         // chunks half*4 .. half*4+3
    const size_t ga = (size_t)(row0 + r) * KD + kc + half * 32;
    const size_t gb = (size_t)(col0 + r) * KD + kc + half * 32;
    #pragma unroll
    for (int i = 0; i < 4; i++) {
        const uint32_t so = SWZ(r, half * 4 + i);
        CP16(sb + so,        Ag + ga + i * 8);
        CP16(sb + SBUF + so, Bg + gb + i * 8);
    }
}

__global__ void __launch_bounds__(256, 2) gemm_fp16(
    const __half* __restrict__ Ag, const __half* __restrict__ Bg,
    float* __restrict__ C, const float* __restrict__ bias, int Cstride)
{
    extern __shared__ char dsm[];
    const uint32_t sbase = smem_u32(dsm);

    const int tid  = threadIdx.x;
    const int wid  = tid >> 5;
    const int lane = tid & 31;
    const int m0 = (wid & 3) * 32;
    const int n0 = (wid >> 2) * 64;
    const int row0 = blockIdx.y * 128;
    const int col0 = blockIdx.x * 128;
    const int lr = lane & 15;
    const int lh = lane >> 4;
    const int r7 = lr & 7;

    uint32_t aRow[2], bRow[4];
    #pragma unroll
    for (int mt = 0; mt < 2; mt++) aRow[mt] = (uint32_t)(m0 + mt * 16 + lr) << 7;
    #pragma unroll
    for (int nt = 0; nt < 4; nt++) bRow[nt] = (uint32_t)(n0 + nt * 16 + lr) << 7;

    float acc[2][8][4];
    #pragma unroll
    for (int i = 0; i < 2; i++)
        #pragma unroll
        for (int j = 0; j < 8; j++)
            #pragma unroll
            for (int q = 0; q < 4; q++) acc[i][j][q] = 0.f;

    // prologue: chunks 0,1 -> stages 0,1
    ld_chunk(sbase,       Ag, Bg, row0, col0, 0,  tid);
    CP_COMMIT();
    ld_chunk(sbase + STG, Ag, Bg, row0, col0, KC, tid);
    CP_COMMIT();

    int stage = 0;
    #pragma unroll 1
    for (int c = 0; c < NCH; c++) {
        CP_WAIT1();            // chunk c resident (own-thread view)
        __syncthreads();       // visible to all; stage (c-1)%3 free

        if (c + 2 < NCH) {
            int ws = stage + 2; if (ws >= NSTG) ws -= NSTG;
            ld_chunk(sbase + ws * STG, Ag, Bg, row0, col0, (c + 2) * KC, tid);
        }
        CP_COMMIT();

        const uint32_t sb = sbase + stage * STG;
        #pragma unroll
        for (int kq = 0; kq < 4; kq++) {
            const uint32_t xp = (uint32_t)(((kq * 2 + lh) ^ r7) << 4);
            uint32_t ah[2][4], bh[4][4];
            #pragma unroll
            for (int mt = 0; mt < 2; mt++)
                LDM4(ah[mt], sb + aRow[mt] + xp);
            #pragma unroll
            for (int nt = 0; nt < 4; nt++)
                LDM4(bh[nt], sb + SBUF + bRow[nt] + xp);
            #pragma unroll
            for (int mt = 0; mt < 2; mt++)
                #pragma unroll
                for (int nt = 0; nt < 4; nt++)
                    #pragma unroll
                    for (int h = 0; h < 2; h++)
                        MMA(acc[mt][nt * 2 + h], ah[mt], bh[nt][h], bh[nt][h + 2]);
        }
        stage++; if (stage >= NSTG) stage = 0;
    }

    // epilogue
    const int l4 = lane >> 2;
    const int l2 = (lane & 3) * 2;
    #pragma unroll
    for (int mt = 0; mt < 2; mt++) {
        #pragma unroll
        for (int j = 0; j < 8; j++) {
            const int grow = row0 + m0 + mt * 16 + l4;
            const int gcol = col0 + n0 + j * 8 + l2;
            float b0 = 0.f, b1 = 0.f;
            if (bias) { b0 = bias[gcol]; b1 = bias[gcol + 1]; }
            float2 v0 = make_float2(acc[mt][j][0] + b0, acc[mt][j][1] + b1);
            float2 v1 = make_float2(acc[mt][j][2] + b0, acc[mt][j][3] + b1);
            *(float2*)(C + (size_t)grow * Cstride + gcol) = v0;
            *(float2*)(C + (size_t)(grow + 8) * Cstride + gcol) = v1;
        }
    }
}

// ---------------------------------------------------------------------------
// Pool V over runs of 32 rows (VY lives in cols [1152,1920) of Y)
// ---------------------------------------------------------------------------
__global__ void pool_v_kernel(const float* __restrict__ Y, float* __restrict__ VBAR)
{
    const int idx = blockIdx.x;
    const int k  = idx & 63;
    const int bh = idx >> 6;
    const int h  = bh % NHEAD;
    const int b  = bh / NHEAD;
    const int d  = threadIdx.x;

    const float* base = Y + ((size_t)(b * SEQ + k * 32)) * NTOT + NAB + h * HD + d;
    float s = 0.f;
    #pragma unroll
    for (int r = 0; r < 32; r++) s += base[(size_t)r * NTOT];
    VBAR[((size_t)bh * NA + k) * HD + d] = s;
}

// ---------------------------------------------------------------------------
// Fused softmax(64) + P @ VBAR(64x64) per query row; writes fp16 ctx.
// ---------------------------------------------------------------------------
__global__ __launch_bounds__(256) void attn_kernel(
    const float* __restrict__ Y, const float* __restrict__ VBAR,
    __half* __restrict__ Ch)
{
    __shared__ __align__(16) float Vs[NA][HD];

    const int bid  = blockIdx.x;
    const int tile = bid & 7;
    const int bh   = bid >> 3;
    const int h    = bh % NHEAD;
    const int b    = bh / NHEAD;

    const float* vb = VBAR + (size_t)bh * (NA * HD);
    for (int t = threadIdx.x * 4; t < NA * HD; t += 256 * 4)
        *(float4*)&Vs[0][t] = *(const float4*)&vb[t];
    __syncthreads();

    const int i   = tile * 256 + threadIdx.x;
    const int row = b * SEQ + i;
    const float* arow = Y + (size_t)row * NTOT + h * NA;
    const float* brow = Y + (size_t)row * NTOT + DIM + h * NB;

    float e[NA];
    #pragma unroll
    for (int k = 0; k < NA; k += 4) {
        float4 v = *(const float4*)&arow[k];
        e[k] = v.x; e[k + 1] = v.y; e[k + 2] = v.z; e[k + 3] = v.w;
    }
    float bb[NB];
    #pragma unroll
    for (int q = 0; q < NB; q += 4) {
        float4 v = *(const float4*)&brow[q];
        bb[q] = v.x; bb[q + 1] = v.y; bb[q + 2] = v.z; bb[q + 3] = v.w;
    }

    float m = -1e30f;
    #pragma unroll
    for (int k = 0; k < NA; k++) {
        e[k] = e[k] * bb[k >> 1];
        m = fmaxf(m, e[k]);
    }
    float s = 0.f;
    #pragma unroll
    for (int k = 0; k < NA; k++) {
        e[k] = __expf(e[k] - m);
        s += e[k];
    }
    const float inv = 1.f / (32.f * s);

    float out[HD];
    #pragma unroll
    for (int d = 0; d < HD; d++) out[d] = 0.f;

    for (int k = 0; k < NA; k++) {
        const float ek = e[k];
        #pragma unroll
        for (int d = 0; d < HD; d += 4) {
            float4 v = *(const float4*)&Vs[k][d];
            out[d + 0] = fmaf(ek, v.x, out[d + 0]);
            out[d + 1] = fmaf(ek, v.y, out[d + 1]);
            out[d + 2] = fmaf(ek, v.z, out[d + 2]);
            out[d + 3] = fmaf(ek, v.w, out[d + 3]);
        }
    }

    const size_t co = (size_t)row * DIM + h * HD;
    #pragma unroll
    for (int d = 0; d < HD; d += 2)
        *(__half2*)(Ch + co + d) = __floats2half2_rn(out[d] * inv, out[d + 1] * inv);
}

// ---------------------------------------------------------------------------
// Launch
// ---------------------------------------------------------------------------
extern "C" void kernel_launch(void* const* d_in, const int* in_sizes, int n_in,
                              void* d_out, int out_size)
{
    const float* x  = (const float*)d_in[0];
    const float* Wa = (const float*)d_in[1];
    const float* Wb = (const float*)d_in[2];
    const float* Wv = (const float*)d_in[3];
    const float* Wp = (const float*)d_in[4];
    const float* bp = (const float*)d_in[5];
    float* out = (float*)d_out;

    float *y, *vbar;
    __half *xh, *ch, *w1, *wp;
    cudaGetSymbolAddress((void**)&y,    g_Y);
    cudaGetSymbolAddress((void**)&vbar, g_VBAR);
    cudaGetSymbolAddress((void**)&xh,   g_Xh);
    cudaGetSymbolAddress((void**)&ch,   g_Ch);
    cudaGetSymbolAddress((void**)&w1,   g_W1);
    cudaGetSymbolAddress((void**)&wp,   g_Wp);

    cudaFuncSetAttribute(gemm_fp16,
                         cudaFuncAttributeMaxDynamicSharedMemorySize, GSMEM);

    dim3 tb(32, 8);
    transpose_cvt<<<dim3(DIM / 32, KD / 32), tb>>>(Wa, DIM, w1, 0);
    transpose_cvt<<<dim3((NHEAD * NB) / 32, KD / 32), tb>>>(Wb, NHEAD * NB, w1, DIM);
    transpose_cvt<<<dim3(DIM / 32, KD / 32), tb>>>(Wv, DIM, w1, NAB);
    transpose_cvt<<<dim3(DIM / 32, KD / 32), tb>>>(Wp, DIM, wp, 0);

    cvt_rows<<<(MROWS * KD) / (256 * 8), 256>>>(x, xh);

    // x @ [Wa|Wb|Wv] -> Y (8192 x 1920)
    gemm_fp16<<<dim3(NTOT / 128, MROWS / 128), 256, GSMEM>>>(
        xh, w1, y, nullptr, NTOT);

    pool_v_kernel<<<BATCH * NHEAD * NA, HD>>>(y, vbar);
    attn_kernel<<<BATCH * NHEAD * (SEQ / 256), 256>>>(y, vbar, ch);

    // ctx @ Wp + bp -> out
    gemm_fp16<<<dim3(DIM / 128, MROWS / 128), 256, GSMEM>>>(
        ch, wp, out, bp, DIM);
}

// round 6
// speedup vs baseline: 4.3283x; 1.0057x over previous
#include <cuda_runtime.h>
#include <cuda_fp16.h>
#include <stdint.h>
#include <math.h>

// ---------------------------------------------------------------------------
// Problem constants
// ---------------------------------------------------------------------------
#define BATCH 4
#define SEQ   2048
#define DIM   768
#define NHEAD 12
#define HD    64
#define NA    64
#define NB    32
#define MROWS 8192
#define KD    768
#define NAB   1152
#define NTOT  1920          // fused [Wa|Wb|Wv] output width

// ---------------------------------------------------------------------------
// Static scratch
// ---------------------------------------------------------------------------
__device__ __align__(256) float g_Y[MROWS * NTOT];          // x@[Wa|Wb|Wv] fp32
__device__ float g_VBAR[BATCH * NHEAD * NA * HD];
__device__ __align__(256) __half g_Xh[MROWS * KD];          // x in fp16
__device__ __align__(256) __half g_Ch[MROWS * KD];          // ctx in fp16
__device__ __align__(256) __half g_W1[NTOT * KD];           // [Wa|Wb|Wv]^T fp16
__device__ __align__(256) __half g_Wp[DIM * KD];            // Wp^T fp16

// ---------------------------------------------------------------------------
// PTX helpers (compute_80-portable)
// ---------------------------------------------------------------------------
__device__ __forceinline__ uint32_t smem_u32(const void* p) {
    uint32_t a;
    asm("{ .reg .u64 t; cvta.to.shared.u64 t, %1; cvt.u32.u64 %0, t; }"
        : "=r"(a) : "l"(p));
    return a;
}

#define CP16(saddr, gptr) \
    asm volatile("cp.async.cg.shared.global [%0], [%1], 16;" \
                 :: "r"(saddr), "l"(gptr) : "memory")
#define CP_COMMIT() asm volatile("cp.async.commit_group;" ::: "memory")
#define CP_WAIT1()  asm volatile("cp.async.wait_group 1;" ::: "memory")

#define LDM4(r, addr) \
    asm volatile("ldmatrix.sync.aligned.m8n8.x4.shared.b16 {%0,%1,%2,%3}, [%4];" \
                 : "=r"((r)[0]), "=r"((r)[1]), "=r"((r)[2]), "=r"((r)[3]) \
                 : "r"(addr))

#define MMA(c, a, b0, b1) \
    asm volatile("mma.sync.aligned.m16n8k16.row.col.f32.f16.f16.f32 " \
                 "{%0,%1,%2,%3}, {%4,%5,%6,%7}, {%8,%9}, {%0,%1,%2,%3};" \
                 : "+f"((c)[0]), "+f"((c)[1]), "+f"((c)[2]), "+f"((c)[3]) \
                 : "r"((a)[0]), "r"((a)[1]), "r"((a)[2]), "r"((a)[3]), \
                   "r"(b0), "r"(b1))

// ---------------------------------------------------------------------------
// Merged prep kernel: x fp32->fp16 convert + all weight transposes.
// Block ranges:
//   [0, 3072)          : x convert (8 elems/thread)
//   [3072, 3072+1440)  : W1 = [Wa|Wb|Wv]^T  (60 n-tiles x 24 k-tiles of 32x32)
//   [4512, 4512+576)   : Wp^T               (24 x 24)
// ---------------------------------------------------------------------------
#define PREP_XBLKS  3072
#define PREP_W1BLKS 1440
#define PREP_WPBLKS 576
#define PREP_BLKS   (PREP_XBLKS + PREP_W1BLKS + PREP_WPBLKS)

__global__ __launch_bounds__(256) void prep_kernel(
    const float* __restrict__ x,  const float* __restrict__ Wa,
    const float* __restrict__ Wb, const float* __restrict__ Wv,
    const float* __restrict__ Wp, __half* __restrict__ Xh,
    __half* __restrict__ W1, __half* __restrict__ WpT)
{
    const int blk = blockIdx.x;
    const int tid = threadIdx.x;

    if (blk < PREP_XBLKS) {
        const int i = (blk * 256 + tid) * 8;
        float4 v0 = *(const float4*)(x + i);
        float4 v1 = *(const float4*)(x + i + 4);
        __half2 h[4];
        h[0] = __floats2half2_rn(v0.x, v0.y);
        h[1] = __floats2half2_rn(v0.z, v0.w);
        h[2] = __floats2half2_rn(v1.x, v1.y);
        h[3] = __floats2half2_rn(v1.z, v1.w);
        *(uint4*)(Xh + i) = *(uint4*)h;
        return;
    }

    __shared__ float tile[32][33];
    const int tx = tid & 31, ty = tid >> 5;

    const float* W;
    __half* T;
    int N, nloc, n0, k0;
    if (blk < PREP_XBLKS + PREP_W1BLKS) {
        const int tb = blk - PREP_XBLKS;
        const int nt = tb % 60, kt = tb / 60;
        n0 = nt * 32; k0 = kt * 32;
        T = W1;
        if (n0 < 768)       { W = Wa; N = 768; nloc = n0; }
        else if (n0 < 1152) { W = Wb; N = 384; nloc = n0 - 768; }
        else                { W = Wv; N = 768; nloc = n0 - 1152; }
    } else {
        const int tb = blk - PREP_XBLKS - PREP_W1BLKS;
        const int nt = tb % 24, kt = tb / 24;
        n0 = nt * 32; k0 = kt * 32;
        T = WpT; W = Wp; N = 768; nloc = n0;
    }

    #pragma unroll
    for (int i = 0; i < 32; i += 8)
        tile[ty + i][tx] = W[(size_t)(k0 + ty + i) * N + nloc + tx];
    __syncthreads();
    #pragma unroll
    for (int i = 0; i < 32; i += 8)
        T[(size_t)(n0 + ty + i) * KD + k0 + tx] =
            __float2half_rn(tile[tx][ty + i]);
}

// ---------------------------------------------------------------------------
// fp16 persistent GEMM: C[M x Ntot] = A @ B^T  (A:[M][K], B:[Ntot][K] fp16)
// CTA tile 128x128, 8 warps (4Mx2N), warp 32x64. K-chunk 64.
// 3-stage SW128-swizzled cp.async pipeline that streams CONTINUOUSLY across
// tile boundaries (next tile's loads overlap current tile's epilogue).
// 96 KB smem -> 2 CTAs/SM. Grid: 304 persistent CTAs.
// ---------------------------------------------------------------------------
#define KC    64
#define NCHT  12              // chunks per tile (KD / KC)
#define SBUF  16384           // 128 rows x 128 B (one matrix, swizzled)
#define STG   (2 * SBUF)      // A + B = 32 KB
#define NSTG  3
#define GSMEM (NSTG * STG)    // 96 KB
#define GGRID 304

#define SWZ(row, ch) (((uint32_t)(row) << 7) + ((((uint32_t)(ch)) ^ ((row) & 7)) << 4))

__device__ __forceinline__ void ld_chunk(
    uint32_t sb, const __half* __restrict__ Ag, const __half* __restrict__ Bg,
    int row0, int col0, int kc, int tid)
{
    const int r    = tid >> 1;
    const int half = tid & 1;
    const size_t ga = (size_t)(row0 + r) * KD + kc + half * 32;
    const size_t gb = (size_t)(col0 + r) * KD + kc + half * 32;
    #pragma unroll
    for (int i = 0; i < 4; i++) {
        const uint32_t so = SWZ(r, half * 4 + i);
        CP16(sb + so,        Ag + ga + i * 8);
        CP16(sb + SBUF + so, Bg + gb + i * 8);
    }
}

__global__ void __launch_bounds__(256, 2) gemm_fp16(
    const __half* __restrict__ Ag, const __half* __restrict__ Bg,
    float* __restrict__ C, const float* __restrict__ bias,
    int Cstride, int ntN, int ntiles)
{
    extern __shared__ char dsm[];
    const uint32_t sbase = smem_u32(dsm);

    const int tid  = threadIdx.x;
    const int wid  = tid >> 5;
    const int lane = tid & 31;
    const int m0 = (wid & 3) * 32;
    const int n0 = (wid >> 2) * 64;
    const int lr = lane & 15;
    const int lh = lane >> 4;
    const int r7 = lr & 7;
    const int bid = blockIdx.x;
    const int G   = gridDim.x;

    const int tcount = (bid < ntiles) ? ((ntiles - 1 - bid) / G + 1) : 0;
    if (tcount == 0) return;
    const int total_g = tcount * NCHT;

    uint32_t aRow[2], bRow[4];
    #pragma unroll
    for (int mt = 0; mt < 2; mt++) aRow[mt] = (uint32_t)(m0 + mt * 16 + lr) << 7;
    #pragma unroll
    for (int nt = 0; nt < 4; nt++) bRow[nt] = (uint32_t)(n0 + nt * 16 + lr) << 7;

    float acc[2][8][4];
    #pragma unroll
    for (int i = 0; i < 2; i++)
        #pragma unroll
        for (int j = 0; j < 8; j++)
            #pragma unroll
            for (int q = 0; q < 4; q++) acc[i][j][q] = 0.f;

    // prologue: global chunks 0,1 (both belong to first tile; NCHT >= 2)
    {
        const int t0 = bid;
        const int r0 = (t0 / ntN) << 7, c0 = (t0 % ntN) << 7;
        ld_chunk(sbase,       Ag, Bg, r0, c0, 0,  tid);
        CP_COMMIT();
        ld_chunk(sbase + STG, Ag, Bg, r0, c0, KC, tid);
        CP_COMMIT();
    }

    int stage = 0;
    #pragma unroll 1
    for (int g = 0; g < total_g; g++) {
        CP_WAIT1();            // chunk g resident (own-thread view)
        __syncthreads();       // visible to all; stage (g-1)%3 free

        const int g2 = g + 2;
        if (g2 < total_g) {
            const int t2 = bid + (g2 / NCHT) * G;
            const int c2 = g2 % NCHT;
            const int r2 = (t2 / ntN) << 7, cc2 = (t2 % ntN) << 7;
            int ws = stage + 2; if (ws >= NSTG) ws -= NSTG;
            ld_chunk(sbase + ws * STG, Ag, Bg, r2, cc2, c2 * KC, tid);
        }
        CP_COMMIT();

        const uint32_t sb = sbase + stage * STG;
        #pragma unroll
        for (int kq = 0; kq < 4; kq++) {
            const uint32_t xp = (uint32_t)(((kq * 2 + lh) ^ r7) << 4);
            uint32_t ah[2][4], bh[4][4];
            #pragma unroll
            for (int mt = 0; mt < 2; mt++)
                LDM4(ah[mt], sb + aRow[mt] + xp);
            #pragma unroll
            for (int nt = 0; nt < 4; nt++)
                LDM4(bh[nt], sb + SBUF + bRow[nt] + xp);
            #pragma unroll
            for (int mt = 0; mt < 2; mt++)
                #pragma unroll
                for (int nt = 0; nt < 4; nt++)
                    #pragma unroll
                    for (int h = 0; h < 2; h++)
                        MMA(acc[mt][nt * 2 + h], ah[mt], bh[nt][h], bh[nt][h + 2]);
        }

        if ((g % NCHT) == NCHT - 1) {
            // epilogue for finished tile (loads for next tile already in flight)
            const int t = bid + (g / NCHT) * G;
            const int row0 = (t / ntN) << 7, col0 = (t % ntN) << 7;
            const int l4 = lane >> 2;
            const int l2 = (lane & 3) * 2;
            #pragma unroll
            for (int mt = 0; mt < 2; mt++) {
                #pragma unroll
                for (int j = 0; j < 8; j++) {
                    const int grow = row0 + m0 + mt * 16 + l4;
                    const int gcol = col0 + n0 + j * 8 + l2;
                    float b0 = 0.f, b1 = 0.f;
                    if (bias) { b0 = bias[gcol]; b1 = bias[gcol + 1]; }
                    float2 v0 = make_float2(acc[mt][j][0] + b0, acc[mt][j][1] + b1);
                    float2 v1 = make_float2(acc[mt][j][2] + b0, acc[mt][j][3] + b1);
                    *(float2*)(C + (size_t)grow * Cstride + gcol) = v0;
                    *(float2*)(C + (size_t)(grow + 8) * Cstride + gcol) = v1;
                    acc[mt][j][0] = 0.f; acc[mt][j][1] = 0.f;
                    acc[mt][j][2] = 0.f; acc[mt][j][3] = 0.f;
                }
            }
        }

        stage++; if (stage >= NSTG) stage = 0;
    }
}

// ---------------------------------------------------------------------------
// Pool V over runs of 32 rows (VY lives in cols [1152,1920) of Y)
// ---------------------------------------------------------------------------
__global__ void pool_v_kernel(const float* __restrict__ Y, float* __restrict__ VBAR)
{
    const int idx = blockIdx.x;
    const int k  = idx & 63;
    const int bh = idx >> 6;
    const int h  = bh % NHEAD;
    const int b  = bh / NHEAD;
    const int d  = threadIdx.x;

    const float* base = Y + ((size_t)(b * SEQ + k * 32)) * NTOT + NAB + h * HD + d;
    float s = 0.f;
    #pragma unroll
    for (int r = 0; r < 32; r++) s += base[(size_t)r * NTOT];
    VBAR[((size_t)bh * NA + k) * HD + d] = s;
}

// ---------------------------------------------------------------------------
// Fused softmax(64) + P @ VBAR(64x64) per query row; writes fp16 ctx.
// ---------------------------------------------------------------------------
__global__ __launch_bounds__(256) void attn_kernel(
    const float* __restrict__ Y, const float* __restrict__ VBAR,
    __half* __restrict__ Ch)
{
    __shared__ __align__(16) float Vs[NA][HD];

    const int bid  = blockIdx.x;
    const int tile = bid & 7;
    const int bh   = bid >> 3;
    const int h    = bh % NHEAD;
    const int b    = bh / NHEAD;

    const float* vb = VBAR + (size_t)bh * (NA * HD);
    for (int t = threadIdx.x * 4; t < NA * HD; t += 256 * 4)
        *(float4*)&Vs[0][t] = *(const float4*)&vb[t];
    __syncthreads();

    const int i   = tile * 256 + threadIdx.x;
    const int row = b * SEQ + i;
    const float* arow = Y + (size_t)row * NTOT + h * NA;
    const float* brow = Y + (size_t)row * NTOT + DIM + h * NB;

    float e[NA];
    #pragma unroll
    for (int k = 0; k < NA; k += 4) {
        float4 v = *(const float4*)&arow[k];
        e[k] = v.x; e[k + 1] = v.y; e[k + 2] = v.z; e[k + 3] = v.w;
    }
    float bb[NB];
    #pragma unroll
    for (int q = 0; q < NB; q += 4) {
        float4 v = *(const float4*)&brow[q];
        bb[q] = v.x; bb[q + 1] = v.y; bb[q + 2] = v.z; bb[q + 3] = v.w;
    }

    float m = -1e30f;
    #pragma unroll
    for (int k = 0; k < NA; k++) {
        e[k] = e[k] * bb[k >> 1];
        m = fmaxf(m, e[k]);
    }
    float s = 0.f;
    #pragma unroll
    for (int k = 0; k < NA; k++) {
        e[k] = __expf(e[k] - m);
        s += e[k];
    }
    const float inv = 1.f / (32.f * s);

    float out[HD];
    #pragma unroll
    for (int d = 0; d < HD; d++) out[d] = 0.f;

    for (int k = 0; k < NA; k++) {
        const float ek = e[k];
        #pragma unroll
        for (int d = 0; d < HD; d += 4) {
            float4 v = *(const float4*)&Vs[k][d];
            out[d + 0] = fmaf(ek, v.x, out[d + 0]);
            out[d + 1] = fmaf(ek, v.y, out[d + 1]);
            out[d + 2] = fmaf(ek, v.z, out[d + 2]);
            out[d + 3] = fmaf(ek, v.w, out[d + 3]);
        }
    }

    const size_t co = (size_t)row * DIM + h * HD;
    #pragma unroll
    for (int d = 0; d < HD; d += 2)
        *(__half2*)(Ch + co + d) = __floats2half2_rn(out[d] * inv, out[d + 1] * inv);
}

// ---------------------------------------------------------------------------
// Launch
// ---------------------------------------------------------------------------
extern "C" void kernel_launch(void* const* d_in, const int* in_sizes, int n_in,
                              void* d_out, int out_size)
{
    const float* x  = (const float*)d_in[0];
    const float* Wa = (const float*)d_in[1];
    const float* Wb = (const float*)d_in[2];
    const float* Wv = (const float*)d_in[3];
    const float* Wp = (const float*)d_in[4];
    const float* bp = (const float*)d_in[5];
    float* out = (float*)d_out;

    float *y, *vbar;
    __half *xh, *ch, *w1, *wp;
    cudaGetSymbolAddress((void**)&y,    g_Y);
    cudaGetSymbolAddress((void**)&vbar, g_VBAR);
    cudaGetSymbolAddress((void**)&xh,   g_Xh);
    cudaGetSymbolAddress((void**)&ch,   g_Ch);
    cudaGetSymbolAddress((void**)&w1,   g_W1);
    cudaGetSymbolAddress((void**)&wp,   g_Wp);

    cudaFuncSetAttribute(gemm_fp16,
                         cudaFuncAttributeMaxDynamicSharedMemorySize, GSMEM);

    // all input conversions + weight transposes in one launch
    prep_kernel<<<PREP_BLKS, 256>>>(x, Wa, Wb, Wv, Wp, xh, w1, wp);

    // x @ [Wa|Wb|Wv] -> Y (8192 x 1920), 960 tiles
    gemm_fp16<<<GGRID, 256, GSMEM>>>(xh, w1, y, nullptr, NTOT, NTOT / 128, 960);

    pool_v_kernel<<<BATCH * NHEAD * NA, HD>>>(y, vbar);
    attn_kernel<<<BATCH * NHEAD * (SEQ / 256), 256>>>(y, vbar, ch);

    // ctx @ Wp + bp -> out (8192 x 768), 384 tiles
    gemm_fp16<<<GGRID, 256, GSMEM>>>(ch, wp, out, bp, DIM, DIM / 128, 384);
}

// round 7
// speedup vs baseline: 5.1005x; 1.1784x over previous
#include <cuda_runtime.h>
#include <cuda_fp16.h>
#include <stdint.h>
#include <math.h>

// ---------------------------------------------------------------------------
// Problem constants
// ---------------------------------------------------------------------------
#define BATCH 4
#define SEQ   2048
#define DIM   768
#define NHEAD 12
#define HD    64
#define NA    64
#define NB    32
#define MROWS 8192
#define KD    768
#define NAB   1152          // fused [Wa|Wb] output width
#define NPOOL 256           // pooled rows (MROWS/32)

// ---------------------------------------------------------------------------
// Static scratch
// ---------------------------------------------------------------------------
__device__ __align__(256) float g_Y[MROWS * NAB];           // x@[Wa|Wb] fp32
__device__ __align__(256) float g_VBAR[NPOOL * DIM];        // pooled-x @ Wv fp32
__device__ __align__(256) __half g_Xh[MROWS * KD];          // x fp16
__device__ __align__(256) __half g_Xbar[NPOOL * KD];        // pooled x fp16
__device__ __align__(256) __half g_Ch[MROWS * KD];          // ctx fp16
__device__ __align__(256) __half g_W1[NAB * KD];            // [Wa|Wb]^T fp16
__device__ __align__(256) __half g_Wv[DIM * KD];            // Wv^T fp16
__device__ __align__(256) __half g_Wp[DIM * KD];            // Wp^T fp16

// ---------------------------------------------------------------------------
// PTX helpers (compute_80-portable)
// ---------------------------------------------------------------------------
__device__ __forceinline__ uint32_t smem_u32(const void* p) {
    uint32_t a;
    asm("{ .reg .u64 t; cvta.to.shared.u64 t, %1; cvt.u32.u64 %0, t; }"
        : "=r"(a) : "l"(p));
    return a;
}

#define CP16(saddr, gptr) \
    asm volatile("cp.async.cg.shared.global [%0], [%1], 16;" \
                 :: "r"(saddr), "l"(gptr) : "memory")
#define CP_COMMIT() asm volatile("cp.async.commit_group;" ::: "memory")
#define CP_WAIT1()  asm volatile("cp.async.wait_group 1;" ::: "memory")

#define LDM4(r, addr) \
    asm volatile("ldmatrix.sync.aligned.m8n8.x4.shared.b16 {%0,%1,%2,%3}, [%4];" \
                 : "=r"((r)[0]), "=r"((r)[1]), "=r"((r)[2]), "=r"((r)[3]) \
                 : "r"(addr))

#define MMA(c, a, b0, b1) \
    asm volatile("mma.sync.aligned.m16n8k16.row.col.f32.f16.f16.f32 " \
                 "{%0,%1,%2,%3}, {%4,%5,%6,%7}, {%8,%9}, {%0,%1,%2,%3};" \
                 : "+f"((c)[0]), "+f"((c)[1]), "+f"((c)[2]), "+f"((c)[3]) \
                 : "r"((a)[0]), "r"((a)[1]), "r"((a)[2]), "r"((a)[3]), \
                   "r"(b0), "r"(b1))

// ---------------------------------------------------------------------------
// Merged prep kernel: x fp32->fp16 + weight transposes (Wa|Wb, Wv, Wp).
// Block ranges:
//   [0, 3072)      : x convert (8 elems/thread)
//   [3072, +864)   : W1 = [Wa|Wb]^T   (36 n-tiles x 24 k-tiles of 32x32)
//   [3936, +576)   : Wv^T             (24 x 24)
//   [4512, +576)   : Wp^T             (24 x 24)
// ---------------------------------------------------------------------------
#define PREP_XBLKS  3072
#define PREP_W1BLKS 864
#define PREP_WVBLKS 576
#define PREP_WPBLKS 576
#define PREP_BLKS   (PREP_XBLKS + PREP_W1BLKS + PREP_WVBLKS + PREP_WPBLKS)

__global__ __launch_bounds__(256) void prep_kernel(
    const float* __restrict__ x,  const float* __restrict__ Wa,
    const float* __restrict__ Wb, const float* __restrict__ Wv,
    const float* __restrict__ Wp, __half* __restrict__ Xh,
    __half* __restrict__ W1, __half* __restrict__ WvT, __half* __restrict__ WpT)
{
    const int blk = blockIdx.x;
    const int tid = threadIdx.x;

    if (blk < PREP_XBLKS) {
        const int i = (blk * 256 + tid) * 8;
        float4 v0 = *(const float4*)(x + i);
        float4 v1 = *(const float4*)(x + i + 4);
        __half2 h[4];
        h[0] = __floats2half2_rn(v0.x, v0.y);
        h[1] = __floats2half2_rn(v0.z, v0.w);
        h[2] = __floats2half2_rn(v1.x, v1.y);
        h[3] = __floats2half2_rn(v1.z, v1.w);
        *(uint4*)(Xh + i) = *(uint4*)h;
        return;
    }

    __shared__ float tile[32][33];
    const int tx = tid & 31, ty = tid >> 5;

    const float* W;
    __half* T;
    int N, nloc, n0, k0;
    int tb = blk - PREP_XBLKS;
    if (tb < PREP_W1BLKS) {
        const int nt = tb % 36, kt = tb / 36;
        n0 = nt * 32; k0 = kt * 32;
        T = W1;
        if (n0 < 768) { W = Wa; N = 768; nloc = n0; }
        else          { W = Wb; N = 384; nloc = n0 - 768; }
    } else if (tb < PREP_W1BLKS + PREP_WVBLKS) {
        tb -= PREP_W1BLKS;
        const int nt = tb % 24, kt = tb / 24;
        n0 = nt * 32; k0 = kt * 32;
        T = WvT; W = Wv; N = 768; nloc = n0;
    } else {
        tb -= PREP_W1BLKS + PREP_WVBLKS;
        const int nt = tb % 24, kt = tb / 24;
        n0 = nt * 32; k0 = kt * 32;
        T = WpT; W = Wp; N = 768; nloc = n0;
    }

    #pragma unroll
    for (int i = 0; i < 32; i += 8)
        tile[ty + i][tx] = W[(size_t)(k0 + ty + i) * N + nloc + tx];
    __syncthreads();
    #pragma unroll
    for (int i = 0; i < 32; i += 8)
        T[(size_t)(n0 + ty + i) * KD + k0 + tx] =
            __float2half_rn(tile[tx][ty + i]);
}

// ---------------------------------------------------------------------------
// Pool x over runs of 32 rows: xbar[p][c] = sum_{r<32} x[32p+r][c]  (fp16 out)
// grid: 256 blocks (one pool row each), 256 threads.
// ---------------------------------------------------------------------------
__global__ __launch_bounds__(256) void pool_x_kernel(
    const float* __restrict__ x, __half* __restrict__ xbar)
{
    const int p = blockIdx.x;
    const int tid = threadIdx.x;
    const float* base = x + (size_t)p * 32 * KD;

    float s0 = 0.f, s1 = 0.f, s2 = 0.f;
    #pragma unroll 4
    for (int r = 0; r < 32; r++) {
        const float* row = base + (size_t)r * KD;
        s0 += row[tid];
        s1 += row[tid + 256];
        s2 += row[tid + 512];
    }
    xbar[(size_t)p * KD + tid]       = __float2half_rn(s0);
    xbar[(size_t)p * KD + tid + 256] = __float2half_rn(s1);
    xbar[(size_t)p * KD + tid + 512] = __float2half_rn(s2);
}

// ---------------------------------------------------------------------------
// fp16 persistent GEMM: C[M x Ntot] = A @ B^T  (A:[M][K], B:[Ntot][K] fp16)
// CTA tile 128x128, 8 warps (4Mx2N), warp 32x64. K-chunk 64.
// 3-stage SW128-swizzled cp.async pipeline streaming across tile boundaries.
// 96 KB smem -> 2 CTAs/SM. Grid: 304 persistent CTAs.
// ---------------------------------------------------------------------------
#define KC    64
#define NCHT  12
#define SBUF  16384
#define STG   (2 * SBUF)
#define NSTG  3
#define GSMEM (NSTG * STG)
#define GGRID 304

#define SWZ(row, ch) (((uint32_t)(row) << 7) + ((((uint32_t)(ch)) ^ ((row) & 7)) << 4))

__device__ __forceinline__ void ld_chunk(
    uint32_t sb, const __half* __restrict__ Ag, const __half* __restrict__ Bg,
    int row0, int col0, int kc, int tid)
{
    const int r    = tid >> 1;
    const int half = tid & 1;
    const size_t ga = (size_t)(row0 + r) * KD + kc + half * 32;
    const size_t gb = (size_t)(col0 + r) * KD + kc + half * 32;
    #pragma unroll
    for (int i = 0; i < 4; i++) {
        const uint32_t so = SWZ(r, half * 4 + i);
        CP16(sb + so,        Ag + ga + i * 8);
        CP16(sb + SBUF + so, Bg + gb + i * 8);
    }
}

__global__ void __launch_bounds__(256, 2) gemm_fp16(
    const __half* __restrict__ Ag, const __half* __restrict__ Bg,
    float* __restrict__ C, const float* __restrict__ bias,
    int Cstride, int ntN, int ntiles)
{
    extern __shared__ char dsm[];
    const uint32_t sbase = smem_u32(dsm);

    const int tid  = threadIdx.x;
    const int wid  = tid >> 5;
    const int lane = tid & 31;
    const int m0 = (wid & 3) * 32;
    const int n0 = (wid >> 2) * 64;
    const int lr = lane & 15;
    const int lh = lane >> 4;
    const int r7 = lr & 7;
    const int bid = blockIdx.x;
    const int G   = gridDim.x;

    const int tcount = (bid < ntiles) ? ((ntiles - 1 - bid) / G + 1) : 0;
    if (tcount == 0) return;
    const int total_g = tcount * NCHT;

    uint32_t aRow[2], bRow[4];
    #pragma unroll
    for (int mt = 0; mt < 2; mt++) aRow[mt] = (uint32_t)(m0 + mt * 16 + lr) << 7;
    #pragma unroll
    for (int nt = 0; nt < 4; nt++) bRow[nt] = (uint32_t)(n0 + nt * 16 + lr) << 7;

    float acc[2][8][4];
    #pragma unroll
    for (int i = 0; i < 2; i++)
        #pragma unroll
        for (int j = 0; j < 8; j++)
            #pragma unroll
            for (int q = 0; q < 4; q++) acc[i][j][q] = 0.f;

    {
        const int t0 = bid;
        const int r0 = (t0 / ntN) << 7, c0 = (t0 % ntN) << 7;
        ld_chunk(sbase,       Ag, Bg, r0, c0, 0,  tid);
        CP_COMMIT();
        ld_chunk(sbase + STG, Ag, Bg, r0, c0, KC, tid);
        CP_COMMIT();
    }

    int stage = 0;
    #pragma unroll 1
    for (int g = 0; g < total_g; g++) {
        CP_WAIT1();
        __syncthreads();

        const int g2 = g + 2;
        if (g2 < total_g) {
            const int t2 = bid + (g2 / NCHT) * G;
            const int c2 = g2 % NCHT;
            const int r2 = (t2 / ntN) << 7, cc2 = (t2 % ntN) << 7;
            int ws = stage + 2; if (ws >= NSTG) ws -= NSTG;
            ld_chunk(sbase + ws * STG, Ag, Bg, r2, cc2, c2 * KC, tid);
        }
        CP_COMMIT();

        const uint32_t sb = sbase + stage * STG;
        #pragma unroll
        for (int kq = 0; kq < 4; kq++) {
            const uint32_t xp = (uint32_t)(((kq * 2 + lh) ^ r7) << 4);
            uint32_t ah[2][4], bh[4][4];
            #pragma unroll
            for (int mt = 0; mt < 2; mt++)
                LDM4(ah[mt], sb + aRow[mt] + xp);
            #pragma unroll
            for (int nt = 0; nt < 4; nt++)
                LDM4(bh[nt], sb + SBUF + bRow[nt] + xp);
            #pragma unroll
            for (int mt = 0; mt < 2; mt++)
                #pragma unroll
                for (int nt = 0; nt < 4; nt++)
                    #pragma unroll
                    for (int h = 0; h < 2; h++)
                        MMA(acc[mt][nt * 2 + h], ah[mt], bh[nt][h], bh[nt][h + 2]);
        }

        if ((g % NCHT) == NCHT - 1) {
            const int t = bid + (g / NCHT) * G;
            const int row0 = (t / ntN) << 7, col0 = (t % ntN) << 7;
            const int l4 = lane >> 2;
            const int l2 = (lane & 3) * 2;
            #pragma unroll
            for (int mt = 0; mt < 2; mt++) {
                #pragma unroll
                for (int j = 0; j < 8; j++) {
                    const int grow = row0 + m0 + mt * 16 + l4;
                    const int gcol = col0 + n0 + j * 8 + l2;
                    float b0 = 0.f, b1 = 0.f;
                    if (bias) { b0 = bias[gcol]; b1 = bias[gcol + 1]; }
                    float2 v0 = make_float2(acc[mt][j][0] + b0, acc[mt][j][1] + b1);
                    float2 v1 = make_float2(acc[mt][j][2] + b0, acc[mt][j][3] + b1);
                    *(float2*)(C + (size_t)grow * Cstride + gcol) = v0;
                    *(float2*)(C + (size_t)(grow + 8) * Cstride + gcol) = v1;
                    acc[mt][j][0] = 0.f; acc[mt][j][1] = 0.f;
                    acc[mt][j][2] = 0.f; acc[mt][j][3] = 0.f;
                }
            }
        }

        stage++; if (stage >= NSTG) stage = 0;
    }
}

// ---------------------------------------------------------------------------
// Fused softmax(64) + P @ VBAR(64x64), spill-free.
// 1 thread = 1 query row. e staged in smem (transposed, conflict-free),
// out computed in two 32-wide register passes. Writes fp16 ctx.
// smem: Vs[64][64] fp32 (16KB) + es[64][256] fp32 (64KB) = 80KB dynamic.
// ---------------------------------------------------------------------------
#define ATTN_SMEM ((64 * 64 + 64 * 256) * 4)

__global__ __launch_bounds__(256) void attn_kernel(
    const float* __restrict__ Y, const float* __restrict__ VB,
    __half* __restrict__ Ch)
{
    extern __shared__ float asm_[];
    float* Vs = asm_;                 // [64][64]
    float* es = asm_ + 64 * 64;       // [64][256]

    const int tid  = threadIdx.x;
    const int bid  = blockIdx.x;
    const int tile = bid & 7;
    const int bh   = bid >> 3;
    const int h    = bh % NHEAD;
    const int b    = bh / NHEAD;

    // load pooled V: Vs[k][d] = VB[(b*64+k)*768 + h*64 + d]
    {
        const float* vb = VB + ((size_t)b * 64) * DIM + h * HD;
        for (int t = tid * 4; t < NA * HD; t += 256 * 4) {
            const int k = t >> 6, d = t & 63;
            *(float4*)&Vs[t] = *(const float4*)(vb + (size_t)k * DIM + d);
        }
    }
    __syncthreads();

    const int i   = tile * 256 + tid;
    const int row = b * SEQ + i;
    const float* arow = Y + (size_t)row * NAB + h * NA;
    const float* brow = Y + (size_t)row * NAB + DIM + h * NB;

    float bb[NB];
    #pragma unroll
    for (int q = 0; q < NB; q += 4) {
        float4 v = *(const float4*)&brow[q];
        bb[q] = v.x; bb[q + 1] = v.y; bb[q + 2] = v.z; bb[q + 3] = v.w;
    }

    // pass 1: max
    float m = -1e30f;
    #pragma unroll
    for (int k = 0; k < NA; k += 4) {
        float4 v = *(const float4*)&arow[k];
        const float c0 = bb[k >> 1], c1 = bb[(k >> 1) + 1];
        m = fmaxf(m, fmaxf(fmaxf(v.x * c0, v.y * c0), fmaxf(v.z * c1, v.w * c1)));
    }

    // pass 2: exp -> smem (transposed), sum
    float s = 0.f;
    #pragma unroll
    for (int k = 0; k < NA; k += 4) {
        float4 v = *(const float4*)&arow[k];
        const float c0 = bb[k >> 1], c1 = bb[(k >> 1) + 1];
        float e0 = __expf(v.x * c0 - m);
        float e1 = __expf(v.y * c0 - m);
        float e2 = __expf(v.z * c1 - m);
        float e3 = __expf(v.w * c1 - m);
        es[(k + 0) * 256 + tid] = e0;
        es[(k + 1) * 256 + tid] = e1;
        es[(k + 2) * 256 + tid] = e2;
        es[(k + 3) * 256 + tid] = e3;
        s += e0 + e1 + e2 + e3;
    }
    const float inv = 1.f / (32.f * s);
    __syncthreads();   // es fully written (only own-thread reads, but keep order)

    const size_t co = (size_t)row * DIM + h * HD;
    #pragma unroll
    for (int h2 = 0; h2 < 2; h2++) {
        float out[32];
        #pragma unroll
        for (int d = 0; d < 32; d++) out[d] = 0.f;

        #pragma unroll 4
        for (int k = 0; k < NA; k++) {
            const float ek = es[k * 256 + tid];
            const float* vrow = Vs + k * 64 + h2 * 32;
            #pragma unroll
            for (int d = 0; d < 32; d += 4) {
                float4 v = *(const float4*)(vrow + d);
                out[d + 0] = fmaf(ek, v.x, out[d + 0]);
                out[d + 1] = fmaf(ek, v.y, out[d + 1]);
                out[d + 2] = fmaf(ek, v.z, out[d + 2]);
                out[d + 3] = fmaf(ek, v.w, out[d + 3]);
            }
        }

        __half2 hv[16];
        #pragma unroll
        for (int d = 0; d < 32; d += 2)
            hv[d >> 1] = __floats2half2_rn(out[d] * inv, out[d + 1] * inv);
        #pragma unroll
        for (int q = 0; q < 4; q++)
            *(uint4*)(Ch + co + h2 * 32 + q * 8) = ((uint4*)hv)[q];
    }
}

// ---------------------------------------------------------------------------
// Launch
// ---------------------------------------------------------------------------
extern "C" void kernel_launch(void* const* d_in, const int* in_sizes, int n_in,
                              void* d_out, int out_size)
{
    const float* x  = (const float*)d_in[0];
    const float* Wa = (const float*)d_in[1];
    const float* Wb = (const float*)d_in[2];
    const float* Wv = (const float*)d_in[3];
    const float* Wp = (const float*)d_in[4];
    const float* bp = (const float*)d_in[5];
    float* out = (float*)d_out;

    float *y, *vbar;
    __half *xh, *xbar, *ch, *w1, *wv, *wp;
    cudaGetSymbolAddress((void**)&y,    g_Y);
    cudaGetSymbolAddress((void**)&vbar, g_VBAR);
    cudaGetSymbolAddress((void**)&xh,   g_Xh);
    cudaGetSymbolAddress((void**)&xbar, g_Xbar);
    cudaGetSymbolAddress((void**)&ch,   g_Ch);
    cudaGetSymbolAddress((void**)&w1,   g_W1);
    cudaGetSymbolAddress((void**)&wv,   g_Wv);
    cudaGetSymbolAddress((void**)&wp,   g_Wp);

    cudaFuncSetAttribute(gemm_fp16,
                         cudaFuncAttributeMaxDynamicSharedMemorySize, GSMEM);
    cudaFuncSetAttribute(attn_kernel,
                         cudaFuncAttributeMaxDynamicSharedMemorySize, ATTN_SMEM);

    // conversions + transposes + pooled x
    prep_kernel<<<PREP_BLKS, 256>>>(x, Wa, Wb, Wv, Wp, xh, w1, wv, wp);
    pool_x_kernel<<<NPOOL, 256>>>(x, xbar);

    // pooled V projection: xbar @ Wv -> vbar (256 x 768), 12 tiles
    gemm_fp16<<<GGRID, 256, GSMEM>>>(xbar, wv, vbar, nullptr, DIM, DIM / 128, 12);

    // x @ [Wa|Wb] -> Y (8192 x 1152), 576 tiles
    gemm_fp16<<<GGRID, 256, GSMEM>>>(xh, w1, y, nullptr, NAB, NAB / 128, 576);

    // fused softmax + P @ Vbar -> ctx fp16
    attn_kernel<<<BATCH * NHEAD * (SEQ / 256), 256, ATTN_SMEM>>>(y, vbar, ch);

    // ctx @ Wp + bp -> out (8192 x 768), 384 tiles
    gemm_fp16<<<GGRID, 256, GSMEM>>>(ch, wp, out, bp, DIM, DIM / 128, 384);
}

// round 8
// speedup vs baseline: 5.8665x; 1.1502x over previous
#include <cuda_runtime.h>
#include <cuda_fp16.h>
#include <stdint.h>
#include <math.h>

// ---------------------------------------------------------------------------
// Problem constants
// ---------------------------------------------------------------------------
#define BATCH 4
#define SEQ   2048
#define DIM   768
#define NHEAD 12
#define HD    64
#define NA    64
#define NB    32
#define MROWS 8192
#define KD    768
#define NAB   1152          // fused [Wa|Wb] output width
#define NPOOL 256           // pooled rows (MROWS/32)

// ---------------------------------------------------------------------------
// Static scratch
// ---------------------------------------------------------------------------
__device__ __align__(256) float g_Y[MROWS * NAB];           // x@[Wa|Wb] fp32
__device__ __align__(256) float g_VBAR[NPOOL * DIM];        // pooled-x @ Wv fp32
__device__ __align__(256) __half g_Xh[MROWS * KD];          // x fp16
__device__ __align__(256) __half g_Xbar[NPOOL * KD];        // pooled x fp16
__device__ __align__(256) __half g_Ch[MROWS * KD];          // ctx fp16
__device__ __align__(256) __half g_W1[NAB * KD];            // [Wa|Wb]^T fp16
__device__ __align__(256) __half g_Wv[DIM * KD];            // Wv^T fp16
__device__ __align__(256) __half g_Wp[DIM * KD];            // Wp^T fp16

// ---------------------------------------------------------------------------
// PTX helpers (compute_80-portable)
// ---------------------------------------------------------------------------
__device__ __forceinline__ uint32_t smem_u32(const void* p) {
    uint32_t a;
    asm("{ .reg .u64 t; cvta.to.shared.u64 t, %1; cvt.u32.u64 %0, t; }"
        : "=r"(a) : "l"(p));
    return a;
}

#define CP16(saddr, gptr) \
    asm volatile("cp.async.cg.shared.global [%0], [%1], 16;" \
                 :: "r"(saddr), "l"(gptr) : "memory")
#define CP_COMMIT() asm volatile("cp.async.commit_group;" ::: "memory")
#define CP_WAIT1()  asm volatile("cp.async.wait_group 1;" ::: "memory")

#define LDM4(r, addr) \
    asm volatile("ldmatrix.sync.aligned.m8n8.x4.shared.b16 {%0,%1,%2,%3}, [%4];" \
                 : "=r"((r)[0]), "=r"((r)[1]), "=r"((r)[2]), "=r"((r)[3]) \
                 : "r"(addr))

#define MMA(c, a, b0, b1) \
    asm volatile("mma.sync.aligned.m16n8k16.row.col.f32.f16.f16.f32 " \
                 "{%0,%1,%2,%3}, {%4,%5,%6,%7}, {%8,%9}, {%0,%1,%2,%3};" \
                 : "+f"((c)[0]), "+f"((c)[1]), "+f"((c)[2]), "+f"((c)[3]) \
                 : "r"((a)[0]), "r"((a)[1]), "r"((a)[2]), "r"((a)[3]), \
                   "r"(b0), "r"(b1))

// ---------------------------------------------------------------------------
// Merged prep kernel: x fp32->fp16 + weight transposes + x pooling.
// Block ranges:
//   [0, 3072)      : x convert (8 elems/thread)
//   [3072, +864)   : W1 = [Wa|Wb]^T   (36 n-tiles x 24 k-tiles of 32x32)
//   [3936, +576)   : Wv^T             (24 x 24)
//   [4512, +576)   : Wp^T             (24 x 24)
//   [5088, +256)   : pool x over 32-row runs -> xbar fp16
// ---------------------------------------------------------------------------
#define PREP_XBLKS   3072
#define PREP_W1BLKS  864
#define PREP_WVBLKS  576
#define PREP_WPBLKS  576
#define PREP_TRBLKS  (PREP_W1BLKS + PREP_WVBLKS + PREP_WPBLKS)
#define PREP_BLKS    (PREP_XBLKS + PREP_TRBLKS + NPOOL)

__global__ __launch_bounds__(256) void prep_kernel(
    const float* __restrict__ x,  const float* __restrict__ Wa,
    const float* __restrict__ Wb, const float* __restrict__ Wv,
    const float* __restrict__ Wp, __half* __restrict__ Xh,
    __half* __restrict__ W1, __half* __restrict__ WvT, __half* __restrict__ WpT,
    __half* __restrict__ xbar)
{
    const int blk = blockIdx.x;
    const int tid = threadIdx.x;

    if (blk < PREP_XBLKS) {
        const int i = (blk * 256 + tid) * 8;
        float4 v0 = *(const float4*)(x + i);
        float4 v1 = *(const float4*)(x + i + 4);
        __half2 h[4];
        h[0] = __floats2half2_rn(v0.x, v0.y);
        h[1] = __floats2half2_rn(v0.z, v0.w);
        h[2] = __floats2half2_rn(v1.x, v1.y);
        h[3] = __floats2half2_rn(v1.z, v1.w);
        *(uint4*)(Xh + i) = *(uint4*)h;
        return;
    }

    if (blk >= PREP_XBLKS + PREP_TRBLKS) {
        // x pooling
        const int p = blk - PREP_XBLKS - PREP_TRBLKS;
        const float* base = x + (size_t)p * 32 * KD;
        float s0 = 0.f, s1 = 0.f, s2 = 0.f;
        #pragma unroll 4
        for (int r = 0; r < 32; r++) {
            const float* row = base + (size_t)r * KD;
            s0 += row[tid];
            s1 += row[tid + 256];
            s2 += row[tid + 512];
        }
        xbar[(size_t)p * KD + tid]       = __float2half_rn(s0);
        xbar[(size_t)p * KD + tid + 256] = __float2half_rn(s1);
        xbar[(size_t)p * KD + tid + 512] = __float2half_rn(s2);
        return;
    }

    __shared__ float tile[32][33];
    const int tx = tid & 31, ty = tid >> 5;

    const float* W;
    __half* T;
    int N, nloc, n0, k0;
    int tb = blk - PREP_XBLKS;
    if (tb < PREP_W1BLKS) {
        const int nt = tb % 36, kt = tb / 36;
        n0 = nt * 32; k0 = kt * 32;
        T = W1;
        if (n0 < 768) { W = Wa; N = 768; nloc = n0; }
        else          { W = Wb; N = 384; nloc = n0 - 768; }
    } else if (tb < PREP_W1BLKS + PREP_WVBLKS) {
        tb -= PREP_W1BLKS;
        const int nt = tb % 24, kt = tb / 24;
        n0 = nt * 32; k0 = kt * 32;
        T = WvT; W = Wv; N = 768; nloc = n0;
    } else {
        tb -= PREP_W1BLKS + PREP_WVBLKS;
        const int nt = tb % 24, kt = tb / 24;
        n0 = nt * 32; k0 = kt * 32;
        T = WpT; W = Wp; N = 768; nloc = n0;
    }

    #pragma unroll
    for (int i = 0; i < 32; i += 8)
        tile[ty + i][tx] = W[(size_t)(k0 + ty + i) * N + nloc + tx];
    __syncthreads();
    #pragma unroll
    for (int i = 0; i < 32; i += 8)
        T[(size_t)(n0 + ty + i) * KD + k0 + tx] =
            __float2half_rn(tile[tx][ty + i]);
}

// ---------------------------------------------------------------------------
// fp16 persistent GEMM with per-tile job mapping.
// MODE 0: tiles [0,576) = Xh@W1^T -> Y (ntN=9, cst=1152)
//         tiles [576,588) = Xbar@Wv^T -> VBAR (ntN=6, cst=768)
// MODE 1: tiles [0,384) = Ch@Wp^T + bias -> out (ntN=6, cst=768)
// CTA tile 128x128, 8 warps (4Mx2N), warp 32x64. K-chunk 64.
// 3-stage SW128-swizzled cp.async pipeline streaming across tile boundaries.
// 96 KB smem -> 2 CTAs/SM. Grid: 304 persistent CTAs.
// ---------------------------------------------------------------------------
#define KC    64
#define NCHT  12
#define SBUF  16384
#define STG   (2 * SBUF)
#define NSTG  3
#define GSMEM (NSTG * STG)
#define GGRID 304

#define SWZ(row, ch) (((uint32_t)(row) << 7) + ((((uint32_t)(ch)) ^ ((row) & 7)) << 4))

__device__ __forceinline__ void ld_chunk(
    uint32_t sb, const __half* __restrict__ Ag, const __half* __restrict__ Bg,
    int row0, int col0, int kc, int tid)
{
    const int r    = tid >> 1;
    const int half = tid & 1;
    const size_t ga = (size_t)(row0 + r) * KD + kc + half * 32;
    const size_t gb = (size_t)(col0 + r) * KD + kc + half * 32;
    #pragma unroll
    for (int i = 0; i < 4; i++) {
        const uint32_t so = SWZ(r, half * 4 + i);
        CP16(sb + so,        Ag + ga + i * 8);
        CP16(sb + SBUF + so, Bg + gb + i * 8);
    }
}

template<int MODE>
__global__ void __launch_bounds__(256, 2) gemm_fp16(
    const __half* __restrict__ A0, const __half* __restrict__ B0,
    float* __restrict__ C0,
    const __half* __restrict__ A1, const __half* __restrict__ B1,
    float* __restrict__ C1,
    const float* __restrict__ bias, int ntiles)
{
    extern __shared__ char dsm[];
    const uint32_t sbase = smem_u32(dsm);

    const int tid  = threadIdx.x;
    const int wid  = tid >> 5;
    const int lane = tid & 31;
    const int m0 = (wid & 3) * 32;
    const int n0 = (wid >> 2) * 64;
    const int lr = lane & 15;
    const int lh = lane >> 4;
    const int r7 = lr & 7;
    const int bid = blockIdx.x;
    const int G   = gridDim.x;

    const int tcount = (bid < ntiles) ? ((ntiles - 1 - bid) / G + 1) : 0;
    if (tcount == 0) return;
    const int total_g = tcount * NCHT;

    // load-side tile mapping (A, B, row0, col0)
    auto tmap_load = [&](int t, const __half*& A, const __half*& B,
                         int& row0, int& col0) {
        if (MODE == 0) {
            if (t < 576) { A = A0; B = B0; row0 = (t / 9) << 7; col0 = (t % 9) << 7; }
            else { int tt = t - 576; A = A1; B = B1;
                   row0 = (tt / 6) << 7; col0 = (tt % 6) << 7; }
        } else {
            A = A0; B = B0; row0 = (t / 6) << 7; col0 = (t % 6) << 7;
        }
    };

    uint32_t aRow[2], bRow[4], xpv[4];
    #pragma unroll
    for (int mt = 0; mt < 2; mt++) aRow[mt] = sbase + ((uint32_t)(m0 + mt * 16 + lr) << 7);
    #pragma unroll
    for (int nt = 0; nt < 4; nt++) bRow[nt] = sbase + SBUF + ((uint32_t)(n0 + nt * 16 + lr) << 7);
    #pragma unroll
    for (int kq = 0; kq < 4; kq++) xpv[kq] = (uint32_t)(((kq * 2 + lh) ^ r7) << 4);

    float acc[2][8][4];
    #pragma unroll
    for (int i = 0; i < 2; i++)
        #pragma unroll
        for (int j = 0; j < 8; j++)
            #pragma unroll
            for (int q = 0; q < 4; q++) acc[i][j][q] = 0.f;

    // prefetch-tile params
    const __half *Ap, *Bp;
    int rowp, colp;
    tmap_load(bid, Ap, Bp, rowp, colp);

    // prologue: chunks 0,1 of first tile
    ld_chunk(sbase,       Ap, Bp, rowp, colp, 0,  tid);
    CP_COMMIT();
    ld_chunk(sbase + STG, Ap, Bp, rowp, colp, KC, tid);
    CP_COMMIT();

    int stage = 0;
    #pragma unroll 1
    for (int g = 0; g < total_g; g++) {
        CP_WAIT1();
        __syncthreads();

        const int g2 = g + 2;
        if (g2 < total_g) {
            const int c2 = g2 % NCHT;
            if (c2 == 0)   // crossed into a new prefetch tile
                tmap_load(bid + (g2 / NCHT) * G, Ap, Bp, rowp, colp);
            int ws = stage + 2; if (ws >= NSTG) ws -= NSTG;
            ld_chunk(sbase + ws * STG, Ap, Bp, rowp, colp, c2 * KC, tid);
        }
        CP_COMMIT();

        const uint32_t so = (uint32_t)(stage * STG);
        #pragma unroll
        for (int kq = 0; kq < 4; kq++) {
            const uint32_t xp = so + xpv[kq];
            uint32_t ah[2][4], bh[4][4];
            #pragma unroll
            for (int mt = 0; mt < 2; mt++)
                LDM4(ah[mt], aRow[mt] + xp);
            #pragma unroll
            for (int nt = 0; nt < 4; nt++)
                LDM4(bh[nt], bRow[nt] + xp);
            #pragma unroll
            for (int mt = 0; mt < 2; mt++)
                #pragma unroll
                for (int nt = 0; nt < 4; nt++)
                    #pragma unroll
                    for (int h = 0; h < 2; h++)
                        MMA(acc[mt][nt * 2 + h], ah[mt], bh[nt][h], bh[nt][h + 2]);
        }

        if ((g % NCHT) == NCHT - 1) {
            // epilogue for finished tile
            const int t = bid + (g / NCHT) * G;
            float* C;
            const float* bs = nullptr;
            int row0, col0, cst;
            if (MODE == 0) {
                if (t < 576) { C = C0; cst = NAB; row0 = (t / 9) << 7; col0 = (t % 9) << 7; }
                else { int tt = t - 576; C = C1; cst = DIM;
                       row0 = (tt / 6) << 7; col0 = (tt % 6) << 7; }
            } else {
                C = C0; cst = DIM; bs = bias;
                row0 = (t / 6) << 7; col0 = (t % 6) << 7;
            }
            const int l4 = lane >> 2;
            const int l2 = (lane & 3) * 2;
            #pragma unroll
            for (int mt = 0; mt < 2; mt++) {
                #pragma unroll
                for (int j = 0; j < 8; j++) {
                    const int grow = row0 + m0 + mt * 16 + l4;
                    const int gcol = col0 + n0 + j * 8 + l2;
                    float b0 = 0.f, b1 = 0.f;
                    if (bs) { b0 = bs[gcol]; b1 = bs[gcol + 1]; }
                    float2 v0 = make_float2(acc[mt][j][0] + b0, acc[mt][j][1] + b1);
                    float2 v1 = make_float2(acc[mt][j][2] + b0, acc[mt][j][3] + b1);
                    *(float2*)(C + (size_t)grow * cst + gcol) = v0;
                    *(float2*)(C + (size_t)(grow + 8) * cst + gcol) = v1;
                    acc[mt][j][0] = 0.f; acc[mt][j][1] = 0.f;
                    acc[mt][j][2] = 0.f; acc[mt][j][3] = 0.f;
                }
            }
        }

        stage++; if (stage >= NSTG) stage = 0;
    }
}

// ---------------------------------------------------------------------------
// Fused softmax(64) + P @ VBAR(64x64), spill-free (es staged in smem).
// ---------------------------------------------------------------------------
#define ATTN_SMEM ((64 * 64 + 64 * 256) * 4)

__global__ __launch_bounds__(256) void attn_kernel(
    const float* __restrict__ Y, const float* __restrict__ VB,
    __half* __restrict__ Ch)
{
    extern __shared__ float asm_[];
    float* Vs = asm_;                 // [64][64]
    float* es = asm_ + 64 * 64;       // [64][256]

    const int tid  = threadIdx.x;
    const int bid  = blockIdx.x;
    const int tile = bid & 7;
    const int bh   = bid >> 3;
    const int h    = bh % NHEAD;
    const int b    = bh / NHEAD;

    {
        const float* vb = VB + ((size_t)b * 64) * DIM + h * HD;
        for (int t = tid * 4; t < NA * HD; t += 256 * 4) {
            const int k = t >> 6, d = t & 63;
            *(float4*)&Vs[t] = *(const float4*)(vb + (size_t)k * DIM + d);
        }
    }
    __syncthreads();

    const int i   = tile * 256 + tid;
    const int row = b * SEQ + i;
    const float* arow = Y + (size_t)row * NAB + h * NA;
    const float* brow = Y + (size_t)row * NAB + DIM + h * NB;

    float bb[NB];
    #pragma unroll
    for (int q = 0; q < NB; q += 4) {
        float4 v = *(const float4*)&brow[q];
        bb[q] = v.x; bb[q + 1] = v.y; bb[q + 2] = v.z; bb[q + 3] = v.w;
    }

    float m = -1e30f;
    #pragma unroll
    for (int k = 0; k < NA; k += 4) {
        float4 v = *(const float4*)&arow[k];
        const float c0 = bb[k >> 1], c1 = bb[(k >> 1) + 1];
        m = fmaxf(m, fmaxf(fmaxf(v.x * c0, v.y * c0), fmaxf(v.z * c1, v.w * c1)));
    }

    float s = 0.f;
    #pragma unroll
    for (int k = 0; k < NA; k += 4) {
        float4 v = *(const float4*)&arow[k];
        const float c0 = bb[k >> 1], c1 = bb[(k >> 1) + 1];
        float e0 = __expf(v.x * c0 - m);
        float e1 = __expf(v.y * c0 - m);
        float e2 = __expf(v.z * c1 - m);
        float e3 = __expf(v.w * c1 - m);
        es[(k + 0) * 256 + tid] = e0;
        es[(k + 1) * 256 + tid] = e1;
        es[(k + 2) * 256 + tid] = e2;
        es[(k + 3) * 256 + tid] = e3;
        s += e0 + e1 + e2 + e3;
    }
    const float inv = 1.f / (32.f * s);
    __syncthreads();

    const size_t co = (size_t)row * DIM + h * HD;
    #pragma unroll
    for (int h2 = 0; h2 < 2; h2++) {
        float out[32];
        #pragma unroll
        for (int d = 0; d < 32; d++) out[d] = 0.f;

        #pragma unroll 4
        for (int k = 0; k < NA; k++) {
            const float ek = es[k * 256 + tid];
            const float* vrow = Vs + k * 64 + h2 * 32;
            #pragma unroll
            for (int d = 0; d < 32; d += 4) {
                float4 v = *(const float4*)(vrow + d);
                out[d + 0] = fmaf(ek, v.x, out[d + 0]);
                out[d + 1] = fmaf(ek, v.y, out[d + 1]);
                out[d + 2] = fmaf(ek, v.z, out[d + 2]);
                out[d + 3] = fmaf(ek, v.w, out[d + 3]);
            }
        }

        __half2 hv[16];
        #pragma unroll
        for (int d = 0; d < 32; d += 2)
            hv[d >> 1] = __floats2half2_rn(out[d] * inv, out[d + 1] * inv);
        #pragma unroll
        for (int q = 0; q < 4; q++)
            *(uint4*)(Ch + co + h2 * 32 + q * 8) = ((uint4*)hv)[q];
    }
}

// ---------------------------------------------------------------------------
// Launch
// ---------------------------------------------------------------------------
extern "C" void kernel_launch(void* const* d_in, const int* in_sizes, int n_in,
                              void* d_out, int out_size)
{
    const float* x  = (const float*)d_in[0];
    const float* Wa = (const float*)d_in[1];
    const float* Wb = (const float*)d_in[2];
    const float* Wv = (const float*)d_in[3];
    const float* Wp = (const float*)d_in[4];
    const float* bp = (const float*)d_in[5];
    float* out = (float*)d_out;

    float *y, *vbar;
    __half *xh, *xbar, *ch, *w1, *wv, *wp;
    cudaGetSymbolAddress((void**)&y,    g_Y);
    cudaGetSymbolAddress((void**)&vbar, g_VBAR);
    cudaGetSymbolAddress((void**)&xh,   g_Xh);
    cudaGetSymbolAddress((void**)&xbar, g_Xbar);
    cudaGetSymbolAddress((void**)&ch,   g_Ch);
    cudaGetSymbolAddress((void**)&w1,   g_W1);
    cudaGetSymbolAddress((void**)&wv,   g_Wv);
    cudaGetSymbolAddress((void**)&wp,   g_Wp);

    cudaFuncSetAttribute(gemm_fp16<0>,
                         cudaFuncAttributeMaxDynamicSharedMemorySize, GSMEM);
    cudaFuncSetAttribute(gemm_fp16<1>,
                         cudaFuncAttributeMaxDynamicSharedMemorySize, GSMEM);
    cudaFuncSetAttribute(attn_kernel,
                         cudaFuncAttributeMaxDynamicSharedMemorySize, ATTN_SMEM);

    // conversions + transposes + pooled x (one launch)
    prep_kernel<<<PREP_BLKS, 256>>>(x, Wa, Wb, Wv, Wp, xh, w1, wv, wp, xbar);

    // merged: x@[Wa|Wb] -> Y (576 tiles) + xbar@Wv -> VBAR (12 tiles)
    gemm_fp16<0><<<GGRID, 256, GSMEM>>>(xh, w1, y, xbar, wv, vbar, nullptr, 588);

    // fused softmax + P @ Vbar -> ctx fp16
    attn_kernel<<<BATCH * NHEAD * (SEQ / 256), 256, ATTN_SMEM>>>(y, vbar, ch);

    // ctx @ Wp + bp -> out (384 tiles)
    gemm_fp16<1><<<GGRID, 256, GSMEM>>>(ch, wp, out, nullptr, nullptr, nullptr, bp, 384);
}

// round 9
// speedup vs baseline: 6.4050x; 1.0918x over previous
#include <cuda_runtime.h>
#include <cuda_fp16.h>
#include <stdint.h>
#include <math.h>

// ---------------------------------------------------------------------------
// Problem constants
// ---------------------------------------------------------------------------
#define BATCH 4
#define SEQ   2048
#define DIM   768
#define NHEAD 12
#define HD    64
#define NA    64
#define NB    32
#define MROWS 8192
#define KD    768
#define NAB   1152
#define NPOOL 256

// ---------------------------------------------------------------------------
// Static scratch
// ---------------------------------------------------------------------------
__device__ __align__(256) float g_Y[MROWS * NAB];
__device__ __align__(256) float g_VBAR[NPOOL * DIM];
__device__ __align__(256) __half g_Xh[MROWS * KD];
__device__ __align__(256) __half g_Xbar[NPOOL * KD];
__device__ __align__(256) __half g_Ch[MROWS * KD];
__device__ __align__(256) __half g_W1[NAB * KD];
__device__ __align__(256) __half g_Wv[DIM * KD];
__device__ __align__(256) __half g_Wp[DIM * KD];

// ---------------------------------------------------------------------------
// PTX helpers
// ---------------------------------------------------------------------------
__device__ __forceinline__ uint32_t smem_u32(const void* p) {
    uint32_t a;
    asm("{ .reg .u64 t; cvta.to.shared.u64 t, %1; cvt.u32.u64 %0, t; }"
        : "=r"(a) : "l"(p));
    return a;
}

#define CP16(saddr, gptr) \
    asm volatile("cp.async.cg.shared.global [%0], [%1], 16;" \
                 :: "r"(saddr), "l"(gptr) : "memory")
#define CP_COMMIT() asm volatile("cp.async.commit_group;" ::: "memory")
#define CP_WAIT1()  asm volatile("cp.async.wait_group 1;" ::: "memory")

#define LDM4(r, addr) \
    asm volatile("ldmatrix.sync.aligned.m8n8.x4.shared.b16 {%0,%1,%2,%3}, [%4];" \
                 : "=r"((r)[0]), "=r"((r)[1]), "=r"((r)[2]), "=r"((r)[3]) \
                 : "r"(addr))

#define MMA(c, a, b0, b1) \
    asm volatile("mma.sync.aligned.m16n8k16.row.col.f32.f16.f16.f32 " \
                 "{%0,%1,%2,%3}, {%4,%5,%6,%7}, {%8,%9}, {%0,%1,%2,%3};" \
                 : "+f"((c)[0]), "+f"((c)[1]), "+f"((c)[2]), "+f"((c)[3]) \
                 : "r"((a)[0]), "r"((a)[1]), "r"((a)[2]), "r"((a)[3]), \
                   "r"(b0), "r"(b1))

// ---------------------------------------------------------------------------
// Merged prep kernel (unchanged from R8)
// ---------------------------------------------------------------------------
#define PREP_XBLKS   3072
#define PREP_W1BLKS  864
#define PREP_WVBLKS  576
#define PREP_WPBLKS  576
#define PREP_TRBLKS  (PREP_W1BLKS + PREP_WVBLKS + PREP_WPBLKS)
#define PREP_BLKS    (PREP_XBLKS + PREP_TRBLKS + NPOOL)

__global__ __launch_bounds__(256) void prep_kernel(
    const float* __restrict__ x,  const float* __restrict__ Wa,
    const float* __restrict__ Wb, const float* __restrict__ Wv,
    const float* __restrict__ Wp, __half* __restrict__ Xh,
    __half* __restrict__ W1, __half* __restrict__ WvT, __half* __restrict__ WpT,
    __half* __restrict__ xbar)
{
    const int blk = blockIdx.x;
    const int tid = threadIdx.x;

    if (blk < PREP_XBLKS) {
        const int i = (blk * 256 + tid) * 8;
        float4 v0 = *(const float4*)(x + i);
        float4 v1 = *(const float4*)(x + i + 4);
        __half2 h[4];
        h[0] = __floats2half2_rn(v0.x, v0.y);
        h[1] = __floats2half2_rn(v0.z, v0.w);
        h[2] = __floats2half2_rn(v1.x, v1.y);
        h[3] = __floats2half2_rn(v1.z, v1.w);
        *(uint4*)(Xh + i) = *(uint4*)h;
        return;
    }

    if (blk >= PREP_XBLKS + PREP_TRBLKS) {
        const int p = blk - PREP_XBLKS - PREP_TRBLKS;
        const float* base = x + (size_t)p * 32 * KD;
        float s0 = 0.f, s1 = 0.f, s2 = 0.f;
        #pragma unroll 4
        for (int r = 0; r < 32; r++) {
            const float* row = base + (size_t)r * KD;
            s0 += row[tid];
            s1 += row[tid + 256];
            s2 += row[tid + 512];
        }
        xbar[(size_t)p * KD + tid]       = __float2half_rn(s0);
        xbar[(size_t)p * KD + tid + 256] = __float2half_rn(s1);
        xbar[(size_t)p * KD + tid + 512] = __float2half_rn(s2);
        return;
    }

    __shared__ float tile[32][33];
    const int tx = tid & 31, ty = tid >> 5;

    const float* W;
    __half* T;
    int N, nloc, n0, k0;
    int tb = blk - PREP_XBLKS;
    if (tb < PREP_W1BLKS) {
        const int nt = tb % 36, kt = tb / 36;
        n0 = nt * 32; k0 = kt * 32;
        T = W1;
        if (n0 < 768) { W = Wa; N = 768; nloc = n0; }
        else          { W = Wb; N = 384; nloc = n0 - 768; }
    } else if (tb < PREP_W1BLKS + PREP_WVBLKS) {
        tb -= PREP_W1BLKS;
        const int nt = tb % 24, kt = tb / 24;
        n0 = nt * 32; k0 = kt * 32;
        T = WvT; W = Wv; N = 768; nloc = n0;
    } else {
        tb -= PREP_W1BLKS + PREP_WVBLKS;
        const int nt = tb % 24, kt = tb / 24;
        n0 = nt * 32; k0 = kt * 32;
        T = WpT; W = Wp; N = 768; nloc = n0;
    }

    #pragma unroll
    for (int i = 0; i < 32; i += 8)
        tile[ty + i][tx] = W[(size_t)(k0 + ty + i) * N + nloc + tx];
    __syncthreads();
    #pragma unroll
    for (int i = 0; i < 32; i += 8)
        T[(size_t)(n0 + ty + i) * KD + k0 + tx] =
            __float2half_rn(tile[tx][ty + i]);
}

// ---------------------------------------------------------------------------
// fp16 persistent GEMM v2: CTA tile 256(M)x128(N), 8 warps (4Mx2N),
// warp tile 64x64, double-buffered ldmatrix fragments, 255-reg budget,
// 1 CTA/SM. K-chunk 64, 3-stage SW128 pipeline streaming across tiles.
// MODE 0: tiles [0,288) Xh@W1 -> Y; [288,294) Xbar@Wv -> VBAR
// MODE 1: tiles [0,192) Ch@Wp + bias -> out
// ---------------------------------------------------------------------------
#define KC    64
#define NCHT  12
#define ABUF  32768            // A: 256 rows x 128 B
#define BBUF  16384            // B: 128 rows x 128 B
#define STG   (ABUF + BBUF)    // 48 KB
#define NSTG  3
#define GSMEM (NSTG * STG)     // 144 KB
#define GGRID 152

#define SWZ(row, ch) (((uint32_t)(row) << 7) + ((((uint32_t)(ch)) ^ ((row) & 7)) << 4))

__device__ __forceinline__ void ld_chunk(
    uint32_t sb, const __half* __restrict__ Ag, const __half* __restrict__ Bg,
    int row0, int col0, int kc, int tid)
{
    const int rr = tid >> 3;          // 0..31
    const int ch = tid & 7;           // 16B column within chunk
    const __half* ap = Ag + (size_t)(row0 + rr) * KD + kc + ch * 8;
    #pragma unroll
    for (int i = 0; i < 8; i++)
        CP16(sb + SWZ(rr + i * 32, ch), ap + (size_t)(i * 32) * KD);
    const __half* bp = Bg + (size_t)(col0 + rr) * KD + kc + ch * 8;
    #pragma unroll
    for (int i = 0; i < 4; i++)
        CP16(sb + ABUF + SWZ(rr + i * 32, ch), bp + (size_t)(i * 32) * KD);
}

template<int MODE>
__global__ void __launch_bounds__(256, 1) gemm_fp16(
    const __half* __restrict__ A0, const __half* __restrict__ B0,
    float* __restrict__ C0,
    const __half* __restrict__ A1, const __half* __restrict__ B1,
    float* __restrict__ C1,
    const float* __restrict__ bias, int ntiles)
{
    extern __shared__ char dsm[];
    const uint32_t sbase = smem_u32(dsm);

    const int tid  = threadIdx.x;
    const int wid  = tid >> 5;
    const int lane = tid & 31;
    const int m0 = (wid & 3) * 64;
    const int n0 = (wid >> 2) * 64;
    const int lr = lane & 15;
    const int lh = lane >> 4;
    const int r7 = lr & 7;
    const int bid = blockIdx.x;
    const int G   = gridDim.x;

    const int tcount = (bid < ntiles) ? ((ntiles - 1 - bid) / G + 1) : 0;
    if (tcount == 0) return;
    const int total_g = tcount * NCHT;

    auto tmap_load = [&](int t, const __half*& A, const __half*& B,
                         int& row0, int& col0) {
        if (MODE == 0) {
            if (t < 288) { A = A0; B = B0; row0 = (t / 9) << 8; col0 = (t % 9) << 7; }
            else { A = A1; B = B1; row0 = 0; col0 = (t - 288) << 7; }
        } else {
            A = A0; B = B0; row0 = (t / 6) << 8; col0 = (t % 6) << 7;
        }
    };

    uint32_t aRow[4], bRow[4], xpv[4];
    #pragma unroll
    for (int mt = 0; mt < 4; mt++)
        aRow[mt] = sbase + ((uint32_t)(m0 + mt * 16 + lr) << 7);
    #pragma unroll
    for (int nt = 0; nt < 4; nt++)
        bRow[nt] = sbase + ABUF + ((uint32_t)(n0 + nt * 16 + lr) << 7);
    #pragma unroll
    for (int kq = 0; kq < 4; kq++)
        xpv[kq] = (uint32_t)(((kq * 2 + lh) ^ r7) << 4);

    float acc[4][8][4];
    #pragma unroll
    for (int i = 0; i < 4; i++)
        #pragma unroll
        for (int j = 0; j < 8; j++)
            #pragma unroll
            for (int q = 0; q < 4; q++) acc[i][j][q] = 0.f;

    const __half *Ap, *Bp;
    int rowp, colp;
    tmap_load(bid, Ap, Bp, rowp, colp);

    ld_chunk(sbase,       Ap, Bp, rowp, colp, 0,  tid);
    CP_COMMIT();
    ld_chunk(sbase + STG, Ap, Bp, rowp, colp, KC, tid);
    CP_COMMIT();

    uint32_t a2[2][4][4], b2[2][4][4];

    int stage = 0;
    #pragma unroll 1
    for (int g = 0; g < total_g; g++) {
        CP_WAIT1();
        __syncthreads();

        const int g2 = g + 2;
        if (g2 < total_g) {
            const int c2 = g2 % NCHT;
            if (c2 == 0)
                tmap_load(bid + (g2 / NCHT) * G, Ap, Bp, rowp, colp);
            int ws = stage + 2; if (ws >= NSTG) ws -= NSTG;
            ld_chunk(sbase + ws * STG, Ap, Bp, rowp, colp, c2 * KC, tid);
        }
        CP_COMMIT();

        const uint32_t so = (uint32_t)(stage * STG);

        // prime fragments for kq = 0
        {
            const uint32_t xp = so + xpv[0];
            #pragma unroll
            for (int mt = 0; mt < 4; mt++) LDM4(a2[0][mt], aRow[mt] + xp);
            #pragma unroll
            for (int nt = 0; nt < 4; nt++) LDM4(b2[0][nt], bRow[nt] + xp);
        }

        #pragma unroll
        for (int kq = 0; kq < 4; kq++) {
            const int cur = kq & 1, nxt = cur ^ 1;
            if (kq < 3) {
                const uint32_t xp = so + xpv[kq + 1];
                #pragma unroll
                for (int mt = 0; mt < 4; mt++) LDM4(a2[nxt][mt], aRow[mt] + xp);
                #pragma unroll
                for (int nt = 0; nt < 4; nt++) LDM4(b2[nxt][nt], bRow[nt] + xp);
            }
            #pragma unroll
            for (int mt = 0; mt < 4; mt++)
                #pragma unroll
                for (int nt = 0; nt < 4; nt++)
                    #pragma unroll
                    for (int h = 0; h < 2; h++)
                        MMA(acc[mt][nt * 2 + h], a2[cur][mt],
                            b2[cur][nt][h], b2[cur][nt][h + 2]);
        }

        if ((g % NCHT) == NCHT - 1) {
            const int t = bid + (g / NCHT) * G;
            float* C;
            const float* bs = nullptr;
            int row0, col0, cst;
            if (MODE == 0) {
                if (t < 288) { C = C0; cst = NAB; row0 = (t / 9) << 8; col0 = (t % 9) << 7; }
                else { C = C1; cst = DIM; row0 = 0; col0 = (t - 288) << 7; }
            } else {
                C = C0; cst = DIM; bs = bias;
                row0 = (t / 6) << 8; col0 = (t % 6) << 7;
            }
            const int l4 = lane >> 2;
            const int l2 = (lane & 3) * 2;
            #pragma unroll
            for (int mt = 0; mt < 4; mt++) {
                #pragma unroll
                for (int j = 0; j < 8; j++) {
                    const int grow = row0 + m0 + mt * 16 + l4;
                    const int gcol = col0 + n0 + j * 8 + l2;
                    float b0 = 0.f, b1 = 0.f;
                    if (bs) { b0 = bs[gcol]; b1 = bs[gcol + 1]; }
                    float2 v0 = make_float2(acc[mt][j][0] + b0, acc[mt][j][1] + b1);
                    float2 v1 = make_float2(acc[mt][j][2] + b0, acc[mt][j][3] + b1);
                    *(float2*)(C + (size_t)grow * cst + gcol) = v0;
                    *(float2*)(C + (size_t)(grow + 8) * cst + gcol) = v1;
                    acc[mt][j][0] = 0.f; acc[mt][j][1] = 0.f;
                    acc[mt][j][2] = 0.f; acc[mt][j][3] = 0.f;
                }
            }
        }

        stage++; if (stage >= NSTG) stage = 0;
    }
}

// ---------------------------------------------------------------------------
// Fused softmax(64) + P @ VBAR(64x64), spill-free (unchanged from R8)
// ---------------------------------------------------------------------------
#define ATTN_SMEM ((64 * 64 + 64 * 256) * 4)

__global__ __launch_bounds__(256) void attn_kernel(
    const float* __restrict__ Y, const float* __restrict__ VB,
    __half* __restrict__ Ch)
{
    extern __shared__ float asm_[];
    float* Vs = asm_;
    float* es = asm_ + 64 * 64;

    const int tid  = threadIdx.x;
    const int bid  = blockIdx.x;
    const int tile = bid & 7;
    const int bh   = bid >> 3;
    const int h    = bh % NHEAD;
    const int b    = bh / NHEAD;

    {
        const float* vb = VB + ((size_t)b * 64) * DIM + h * HD;
        for (int t = tid * 4; t < NA * HD; t += 256 * 4) {
            const int k = t >> 6, d = t & 63;
            *(float4*)&Vs[t] = *(const float4*)(vb + (size_t)k * DIM + d);
        }
    }
    __syncthreads();

    const int i   = tile * 256 + tid;
    const int row = b * SEQ + i;
    const float* arow = Y + (size_t)row * NAB + h * NA;
    const float* brow = Y + (size_t)row * NAB + DIM + h * NB;

    float bb[NB];
    #pragma unroll
    for (int q = 0; q < NB; q += 4) {
        float4 v = *(const float4*)&brow[q];
        bb[q] = v.x; bb[q + 1] = v.y; bb[q + 2] = v.z; bb[q + 3] = v.w;
    }

    float m = -1e30f;
    #pragma unroll
    for (int k = 0; k < NA; k += 4) {
        float4 v = *(const float4*)&arow[k];
        const float c0 = bb[k >> 1], c1 = bb[(k >> 1) + 1];
        m = fmaxf(m, fmaxf(fmaxf(v.x * c0, v.y * c0), fmaxf(v.z * c1, v.w * c1)));
    }

    float s = 0.f;
    #pragma unroll
    for (int k = 0; k < NA; k += 4) {
        float4 v = *(const float4*)&arow[k];
        const float c0 = bb[k >> 1], c1 = bb[(k >> 1) + 1];
        float e0 = __expf(v.x * c0 - m);
        float e1 = __expf(v.y * c0 - m);
        float e2 = __expf(v.z * c1 - m);
        float e3 = __expf(v.w * c1 - m);
        es[(k + 0) * 256 + tid] = e0;
        es[(k + 1) * 256 + tid] = e1;
        es[(k + 2) * 256 + tid] = e2;
        es[(k + 3) * 256 + tid] = e3;
        s += e0 + e1 + e2 + e3;
    }
    const float inv = 1.f / (32.f * s);
    __syncthreads();

    const size_t co = (size_t)row * DIM + h * HD;
    #pragma unroll
    for (int h2 = 0; h2 < 2; h2++) {
        float out[32];
        #pragma unroll
        for (int d = 0; d < 32; d++) out[d] = 0.f;

        #pragma unroll 4
        for (int k = 0; k < NA; k++) {
            const float ek = es[k * 256 + tid];
            const float* vrow = Vs + k * 64 + h2 * 32;
            #pragma unroll
            for (int d = 0; d < 32; d += 4) {
                float4 v = *(const float4*)(vrow + d);
                out[d + 0] = fmaf(ek, v.x, out[d + 0]);
                out[d + 1] = fmaf(ek, v.y, out[d + 1]);
                out[d + 2] = fmaf(ek, v.z, out[d + 2]);
                out[d + 3] = fmaf(ek, v.w, out[d + 3]);
            }
        }

        __half2 hv[16];
        #pragma unroll
        for (int d = 0; d < 32; d += 2)
            hv[d >> 1] = __floats2half2_rn(out[d] * inv, out[d + 1] * inv);
        #pragma unroll
        for (int q = 0; q < 4; q++)
            *(uint4*)(Ch + co + h2 * 32 + q * 8) = ((uint4*)hv)[q];
    }
}

// ---------------------------------------------------------------------------
// Launch
// ---------------------------------------------------------------------------
extern "C" void kernel_launch(void* const* d_in, const int* in_sizes, int n_in,
                              void* d_out, int out_size)
{
    const float* x  = (const float*)d_in[0];
    const float* Wa = (const float*)d_in[1];
    const float* Wb = (const float*)d_in[2];
    const float* Wv = (const float*)d_in[3];
    const float* Wp = (const float*)d_in[4];
    const float* bp = (const float*)d_in[5];
    float* out = (float*)d_out;

    float *y, *vbar;
    __half *xh, *xbar, *ch, *w1, *wv, *wp;
    cudaGetSymbolAddress((void**)&y,    g_Y);
    cudaGetSymbolAddress((void**)&vbar, g_VBAR);
    cudaGetSymbolAddress((void**)&xh,   g_Xh);
    cudaGetSymbolAddress((void**)&xbar, g_Xbar);
    cudaGetSymbolAddress((void**)&ch,   g_Ch);
    cudaGetSymbolAddress((void**)&w1,   g_W1);
    cudaGetSymbolAddress((void**)&wv,   g_Wv);
    cudaGetSymbolAddress((void**)&wp,   g_Wp);

    cudaFuncSetAttribute(gemm_fp16<0>,
                         cudaFuncAttributeMaxDynamicSharedMemorySize, GSMEM);
    cudaFuncSetAttribute(gemm_fp16<1>,
                         cudaFuncAttributeMaxDynamicSharedMemorySize, GSMEM);
    cudaFuncSetAttribute(attn_kernel,
                         cudaFuncAttributeMaxDynamicSharedMemorySize, ATTN_SMEM);

    prep_kernel<<<PREP_BLKS, 256>>>(x, Wa, Wb, Wv, Wp, xh, w1, wv, wp, xbar);

    // merged: x@[Wa|Wb] -> Y (288 tiles) + xbar@Wv -> VBAR (6 tiles)
    gemm_fp16<0><<<GGRID, 256, GSMEM>>>(xh, w1, y, xbar, wv, vbar, nullptr, 294);

    attn_kernel<<<BATCH * NHEAD * (SEQ / 256), 256, ATTN_SMEM>>>(y, vbar, ch);

    // ctx @ Wp + bp -> out (192 tiles)
    gemm_fp16<1><<<GGRID, 256, GSMEM>>>(ch, wp, out, nullptr, nullptr, nullptr, bp, 192);
}

// round 10
// speedup vs baseline: 6.6707x; 1.0415x over previous
#include <cuda_runtime.h>
#include <cuda_fp16.h>
#include <stdint.h>
#include <math.h>

// ---------------------------------------------------------------------------
// Problem constants
// ---------------------------------------------------------------------------
#define BATCH 4
#define SEQ   2048
#define DIM   768
#define NHEAD 12
#define HD    64
#define NA    64
#define NB    32
#define MROWS 8192
#define KD    768
#define NAB   1152
#define NPOOL 256

// ---------------------------------------------------------------------------
// Static scratch
// ---------------------------------------------------------------------------
__device__ __align__(256) __half g_Yh[MROWS * NAB];         // x@[Wa|Wb] fp16
__device__ __align__(256) float g_VBAR[NPOOL * DIM];
__device__ __align__(256) __half g_Xh[MROWS * KD];
__device__ __align__(256) __half g_Xbar[NPOOL * KD];
__device__ __align__(256) __half g_Ch[MROWS * KD];
__device__ __align__(256) __half g_W1[NAB * KD];
__device__ __align__(256) __half g_Wv[DIM * KD];
__device__ __align__(256) __half g_Wp[DIM * KD];

// ---------------------------------------------------------------------------
// PTX helpers
// ---------------------------------------------------------------------------
__device__ __forceinline__ uint32_t smem_u32(const void* p) {
    uint32_t a;
    asm("{ .reg .u64 t; cvta.to.shared.u64 t, %1; cvt.u32.u64 %0, t; }"
        : "=r"(a) : "l"(p));
    return a;
}

#define CP16(saddr, gptr) \
    asm volatile("cp.async.cg.shared.global [%0], [%1], 16;" \
                 :: "r"(saddr), "l"(gptr) : "memory")
#define CP_COMMIT() asm volatile("cp.async.commit_group;" ::: "memory")
#define CP_WAIT1()  asm volatile("cp.async.wait_group 1;" ::: "memory")

#define LDM4(r, addr) \
    asm volatile("ldmatrix.sync.aligned.m8n8.x4.shared.b16 {%0,%1,%2,%3}, [%4];" \
                 : "=r"((r)[0]), "=r"((r)[1]), "=r"((r)[2]), "=r"((r)[3]) \
                 : "r"(addr))

#define MMA(c, a, b0, b1) \
    asm volatile("mma.sync.aligned.m16n8k16.row.col.f32.f16.f16.f32 " \
                 "{%0,%1,%2,%3}, {%4,%5,%6,%7}, {%8,%9}, {%0,%1,%2,%3};" \
                 : "+f"((c)[0]), "+f"((c)[1]), "+f"((c)[2]), "+f"((c)[3]) \
                 : "r"((a)[0]), "r"((a)[1]), "r"((a)[2]), "r"((a)[3]), \
                   "r"(b0), "r"(b1))

// ---------------------------------------------------------------------------
// Merged prep kernel (unchanged)
// ---------------------------------------------------------------------------
#define PREP_XBLKS   3072
#define PREP_W1BLKS  864
#define PREP_WVBLKS  576
#define PREP_WPBLKS  576
#define PREP_TRBLKS  (PREP_W1BLKS + PREP_WVBLKS + PREP_WPBLKS)
#define PREP_BLKS    (PREP_XBLKS + PREP_TRBLKS + NPOOL)

__global__ __launch_bounds__(256) void prep_kernel(
    const float* __restrict__ x,  const float* __restrict__ Wa,
    const float* __restrict__ Wb, const float* __restrict__ Wv,
    const float* __restrict__ Wp, __half* __restrict__ Xh,
    __half* __restrict__ W1, __half* __restrict__ WvT, __half* __restrict__ WpT,
    __half* __restrict__ xbar)
{
    const int blk = blockIdx.x;
    const int tid = threadIdx.x;

    if (blk < PREP_XBLKS) {
        const int i = (blk * 256 + tid) * 8;
        float4 v0 = *(const float4*)(x + i);
        float4 v1 = *(const float4*)(x + i + 4);
        __half2 h[4];
        h[0] = __floats2half2_rn(v0.x, v0.y);
        h[1] = __floats2half2_rn(v0.z, v0.w);
        h[2] = __floats2half2_rn(v1.x, v1.y);
        h[3] = __floats2half2_rn(v1.z, v1.w);
        *(uint4*)(Xh + i) = *(uint4*)h;
        return;
    }

    if (blk >= PREP_XBLKS + PREP_TRBLKS) {
        const int p = blk - PREP_XBLKS - PREP_TRBLKS;
        const float* base = x + (size_t)p * 32 * KD;
        float s0 = 0.f, s1 = 0.f, s2 = 0.f;
        #pragma unroll 4
        for (int r = 0; r < 32; r++) {
            const float* row = base + (size_t)r * KD;
            s0 += row[tid];
            s1 += row[tid + 256];
            s2 += row[tid + 512];
        }
        xbar[(size_t)p * KD + tid]       = __float2half_rn(s0);
        xbar[(size_t)p * KD + tid + 256] = __float2half_rn(s1);
        xbar[(size_t)p * KD + tid + 512] = __float2half_rn(s2);
        return;
    }

    __shared__ float tile[32][33];
    const int tx = tid & 31, ty = tid >> 5;

    const float* W;
    __half* T;
    int N, nloc, n0, k0;
    int tb = blk - PREP_XBLKS;
    if (tb < PREP_W1BLKS) {
        const int nt = tb % 36, kt = tb / 36;
        n0 = nt * 32; k0 = kt * 32;
        T = W1;
        if (n0 < 768) { W = Wa; N = 768; nloc = n0; }
        else          { W = Wb; N = 384; nloc = n0 - 768; }
    } else if (tb < PREP_W1BLKS + PREP_WVBLKS) {
        tb -= PREP_W1BLKS;
        const int nt = tb % 24, kt = tb / 24;
        n0 = nt * 32; k0 = kt * 32;
        T = WvT; W = Wv; N = 768; nloc = n0;
    } else {
        tb -= PREP_W1BLKS + PREP_WVBLKS;
        const int nt = tb % 24, kt = tb / 24;
        n0 = nt * 32; k0 = kt * 32;
        T = WpT; W = Wp; N = 768; nloc = n0;
    }

    #pragma unroll
    for (int i = 0; i < 32; i += 8)
        tile[ty + i][tx] = W[(size_t)(k0 + ty + i) * N + nloc + tx];
    __syncthreads();
    #pragma unroll
    for (int i = 0; i < 32; i += 8)
        T[(size_t)(n0 + ty + i) * KD + k0 + tx] =
            __float2half_rn(tile[tx][ty + i]);
}

// ---------------------------------------------------------------------------
// fp16 persistent GEMM v3: CTA 256x128, 512 threads, 16 warps (4Mx4N),
// warp tile 64x32 -> 4 warps/SMSP for latency hiding, <=128 regs/thread.
// K-chunk 64, 3-stage SW128 pipeline streaming across tiles, 144 KB smem.
// MODE 0: tiles [0,288) Xh@W1 -> Yh (fp16); [288,294) Xbar@Wv -> VBAR (fp32)
// MODE 1: tiles [0,192) Ch@Wp + bias -> out (fp32)
// ---------------------------------------------------------------------------
#define KC    64
#define NCHT  12
#define ABUF  32768
#define BBUF  16384
#define STG   (ABUF + BBUF)
#define NSTG  3
#define GSMEM (NSTG * STG)
#define GGRID 152
#define GTHR  512

#define SWZ(row, ch) (((uint32_t)(row) << 7) + ((((uint32_t)(ch)) ^ ((row) & 7)) << 4))

__device__ __forceinline__ void ld_chunk(
    uint32_t sb, const __half* __restrict__ Ag, const __half* __restrict__ Bg,
    int row0, int col0, int kc, int tid)
{
    const int rr = tid >> 3;          // 0..63
    const int ch = tid & 7;
    const __half* ap = Ag + (size_t)(row0 + rr) * KD + kc + ch * 8;
    #pragma unroll
    for (int i = 0; i < 4; i++)
        CP16(sb + SWZ(rr + i * 64, ch), ap + (size_t)(i * 64) * KD);
    const __half* bp = Bg + (size_t)(col0 + rr) * KD + kc + ch * 8;
    #pragma unroll
    for (int i = 0; i < 2; i++)
        CP16(sb + ABUF + SWZ(rr + i * 64, ch), bp + (size_t)(i * 64) * KD);
}

template<int MODE>
__global__ void __launch_bounds__(GTHR, 1) gemm_fp16(
    const __half* __restrict__ A0, const __half* __restrict__ B0,
    void* __restrict__ C0v,
    const __half* __restrict__ A1, const __half* __restrict__ B1,
    float* __restrict__ C1,
    const float* __restrict__ bias, int ntiles)
{
    extern __shared__ char dsm[];
    const uint32_t sbase = smem_u32(dsm);

    const int tid  = threadIdx.x;
    const int wid  = tid >> 5;
    const int lane = tid & 31;
    const int m0 = (wid & 3) * 64;     // 4 M-groups
    const int n0 = (wid >> 2) * 32;    // 4 N-groups
    const int lr = lane & 15;
    const int lh = lane >> 4;
    const int r7 = lr & 7;
    const int bid = blockIdx.x;
    const int G   = gridDim.x;

    const int tcount = (bid < ntiles) ? ((ntiles - 1 - bid) / G + 1) : 0;
    if (tcount == 0) return;
    const int total_g = tcount * NCHT;

    auto tmap_load = [&](int t, const __half*& A, const __half*& B,
                         int& row0, int& col0) {
        if (MODE == 0) {
            if (t < 288) { A = A0; B = B0; row0 = (t / 9) << 8; col0 = (t % 9) << 7; }
            else { A = A1; B = B1; row0 = 0; col0 = (t - 288) << 7; }
        } else {
            A = A0; B = B0; row0 = (t / 6) << 8; col0 = (t % 6) << 7;
        }
    };

    uint32_t aRow[4], bRow[2];
    #pragma unroll
    for (int mt = 0; mt < 4; mt++)
        aRow[mt] = sbase + ((uint32_t)(m0 + mt * 16 + lr) << 7);
    #pragma unroll
    for (int nt = 0; nt < 2; nt++)
        bRow[nt] = sbase + ABUF + ((uint32_t)(n0 + nt * 16 + lr) << 7);

    float acc[4][4][4];
    #pragma unroll
    for (int i = 0; i < 4; i++)
        #pragma unroll
        for (int j = 0; j < 4; j++)
            #pragma unroll
            for (int q = 0; q < 4; q++) acc[i][j][q] = 0.f;

    const __half *Ap, *Bp;
    int rowp, colp;
    tmap_load(bid, Ap, Bp, rowp, colp);

    ld_chunk(sbase,       Ap, Bp, rowp, colp, 0,  tid);
    CP_COMMIT();
    ld_chunk(sbase + STG, Ap, Bp, rowp, colp, KC, tid);
    CP_COMMIT();

    int stage = 0;
    #pragma unroll 1
    for (int g = 0; g < total_g; g++) {
        CP_WAIT1();
        __syncthreads();

        const int g2 = g + 2;
        if (g2 < total_g) {
            const int c2 = g2 % NCHT;
            if (c2 == 0)
                tmap_load(bid + (g2 / NCHT) * G, Ap, Bp, rowp, colp);
            int ws = stage + 2; if (ws >= NSTG) ws -= NSTG;
            ld_chunk(sbase + ws * STG, Ap, Bp, rowp, colp, c2 * KC, tid);
        }
        CP_COMMIT();

        const uint32_t so = (uint32_t)(stage * STG);
        #pragma unroll
        for (int kq = 0; kq < 4; kq++) {
            const uint32_t xp = so + (uint32_t)(((kq * 2 + lh) ^ r7) << 4);
            uint32_t af[4][4], bf[2][4];
            #pragma unroll
            for (int mt = 0; mt < 4; mt++) LDM4(af[mt], aRow[mt] + xp);
            #pragma unroll
            for (int nt = 0; nt < 2; nt++) LDM4(bf[nt], bRow[nt] + xp);
            #pragma unroll
            for (int mt = 0; mt < 4; mt++)
                #pragma unroll
                for (int nt = 0; nt < 2; nt++)
                    #pragma unroll
                    for (int h = 0; h < 2; h++)
                        MMA(acc[mt][nt * 2 + h], af[mt], bf[nt][h], bf[nt][h + 2]);
        }

        if ((g % NCHT) == NCHT - 1) {
            const int t = bid + (g / NCHT) * G;
            const int l4 = lane >> 2;
            const int l2 = (lane & 3) * 2;
            if (MODE == 0 && t < 288) {
                __half* C = (__half*)C0v;
                const int row0 = (t / 9) << 8, col0 = (t % 9) << 7;
                #pragma unroll
                for (int mt = 0; mt < 4; mt++)
                    #pragma unroll
                    for (int j = 0; j < 4; j++) {
                        const int grow = row0 + m0 + mt * 16 + l4;
                        const int gcol = col0 + n0 + j * 8 + l2;
                        *(__half2*)(C + (size_t)grow * NAB + gcol) =
                            __floats2half2_rn(acc[mt][j][0], acc[mt][j][1]);
                        *(__half2*)(C + (size_t)(grow + 8) * NAB + gcol) =
                            __floats2half2_rn(acc[mt][j][2], acc[mt][j][3]);
                        acc[mt][j][0] = 0.f; acc[mt][j][1] = 0.f;
                        acc[mt][j][2] = 0.f; acc[mt][j][3] = 0.f;
                    }
            } else if (MODE == 0) {
                float* C = C1;
                const int col0 = (t - 288) << 7;
                #pragma unroll
                for (int mt = 0; mt < 4; mt++)
                    #pragma unroll
                    for (int j = 0; j < 4; j++) {
                        const int grow = m0 + mt * 16 + l4;
                        const int gcol = col0 + n0 + j * 8 + l2;
                        *(float2*)(C + (size_t)grow * DIM + gcol) =
                            make_float2(acc[mt][j][0], acc[mt][j][1]);
                        *(float2*)(C + (size_t)(grow + 8) * DIM + gcol) =
                            make_float2(acc[mt][j][2], acc[mt][j][3]);
                        acc[mt][j][0] = 0.f; acc[mt][j][1] = 0.f;
                        acc[mt][j][2] = 0.f; acc[mt][j][3] = 0.f;
                    }
            } else {
                float* C = (float*)C0v;
                const int row0 = (t / 6) << 8, col0 = (t % 6) << 7;
                #pragma unroll
                for (int mt = 0; mt < 4; mt++)
                    #pragma unroll
                    for (int j = 0; j < 4; j++) {
                        const int grow = row0 + m0 + mt * 16 + l4;
                        const int gcol = col0 + n0 + j * 8 + l2;
                        const float b0 = bias[gcol], b1 = bias[gcol + 1];
                        *(float2*)(C + (size_t)grow * DIM + gcol) =
                            make_float2(acc[mt][j][0] + b0, acc[mt][j][1] + b1);
                        *(float2*)(C + (size_t)(grow + 8) * DIM + gcol) =
                            make_float2(acc[mt][j][2] + b0, acc[mt][j][3] + b1);
                        acc[mt][j][0] = 0.f; acc[mt][j][1] = 0.f;
                        acc[mt][j][2] = 0.f; acc[mt][j][3] = 0.f;
                    }
            }
        }

        stage++; if (stage >= NSTG) stage = 0;
    }
}

// ---------------------------------------------------------------------------
// Fused softmax(64) + P @ VBAR(64x64); Y now fp16. Spill-free (es in smem).
// ---------------------------------------------------------------------------
#define ATTN_SMEM ((64 * 64 + 64 * 256) * 4)

__global__ __launch_bounds__(256) void attn_kernel(
    const __half* __restrict__ Y, const float* __restrict__ VB,
    __half* __restrict__ Ch)
{
    extern __shared__ float asm_[];
    float* Vs = asm_;
    float* es = asm_ + 64 * 64;

    const int tid  = threadIdx.x;
    const int bid  = blockIdx.x;
    const int tile = bid & 7;
    const int bh   = bid >> 3;
    const int h    = bh % NHEAD;
    const int b    = bh / NHEAD;

    {
        const float* vb = VB + ((size_t)b * 64) * DIM + h * HD;
        for (int t = tid * 4; t < NA * HD; t += 256 * 4) {
            const int k = t >> 6, d = t & 63;
            *(float4*)&Vs[t] = *(const float4*)(vb + (size_t)k * DIM + d);
        }
    }
    __syncthreads();

    const int i   = tile * 256 + tid;
    const int row = b * SEQ + i;
    const __half* arow = Y + (size_t)row * NAB + h * NA;
    const __half* brow = Y + (size_t)row * NAB + DIM + h * NB;

    float bb[NB];
    {
        const uint4* b4 = (const uint4*)brow;
        #pragma unroll
        for (int q8 = 0; q8 < 4; q8++) {
            uint4 u = b4[q8];
            const __half2* hp = (const __half2*)&u;
            #pragma unroll
            for (int q = 0; q < 4; q++) {
                float2 f = __half22float2(hp[q]);
                bb[q8 * 8 + q * 2]     = f.x;
                bb[q8 * 8 + q * 2 + 1] = f.y;
            }
        }
    }

    const uint4* a4 = (const uint4*)arow;

    // pass 1: max  (score pair (2q,2q+1) shares bb[q])
    float m = -1e30f;
    #pragma unroll
    for (int k8 = 0; k8 < 8; k8++) {
        uint4 u = a4[k8];
        const __half2* hp = (const __half2*)&u;
        #pragma unroll
        for (int q = 0; q < 4; q++) {
            float2 af = __half22float2(hp[q]);
            const float c = bb[(k8 * 8 + q * 2) >> 1];
            m = fmaxf(m, fmaxf(af.x * c, af.y * c));
        }
    }

    // pass 2: exp -> smem (transposed), sum
    float s = 0.f;
    #pragma unroll
    for (int k8 = 0; k8 < 8; k8++) {
        uint4 u = a4[k8];
        const __half2* hp = (const __half2*)&u;
        #pragma unroll
        for (int q = 0; q < 4; q++) {
            float2 af = __half22float2(hp[q]);
            const int k = k8 * 8 + q * 2;
            const float c = bb[k >> 1];
            float e0 = __expf(af.x * c - m);
            float e1 = __expf(af.y * c - m);
            es[(k + 0) * 256 + tid] = e0;
            es[(k + 1) * 256 + tid] = e1;
            s += e0 + e1;
        }
    }
    const float inv = 1.f / (32.f * s);
    __syncthreads();

    const size_t co = (size_t)row * DIM + h * HD;
    #pragma unroll
    for (int h2 = 0; h2 < 2; h2++) {
        float out[32];
        #pragma unroll
        for (int d = 0; d < 32; d++) out[d] = 0.f;

        #pragma unroll 4
        for (int k = 0; k < NA; k++) {
            const float ek = es[k * 256 + tid];
            const float* vrow = Vs + k * 64 + h2 * 32;
            #pragma unroll
            for (int d = 0; d < 32; d += 4) {
                float4 v = *(const float4*)(vrow + d);
                out[d + 0] = fmaf(ek, v.x, out[d + 0]);
                out[d + 1] = fmaf(ek, v.y, out[d + 1]);
                out[d + 2] = fmaf(ek, v.z, out[d + 2]);
                out[d + 3] = fmaf(ek, v.w, out[d + 3]);
            }
        }

        __half2 hv[16];
        #pragma unroll
        for (int d = 0; d < 32; d += 2)
            hv[d >> 1] = __floats2half2_rn(out[d] * inv, out[d + 1] * inv);
        #pragma unroll
        for (int q = 0; q < 4; q++)
            *(uint4*)(Ch + co + h2 * 32 + q * 8) = ((uint4*)hv)[q];
    }
}

// ---------------------------------------------------------------------------
// Launch
// ---------------------------------------------------------------------------
extern "C" void kernel_launch(void* const* d_in, const int* in_sizes, int n_in,
                              void* d_out, int out_size)
{
    const float* x  = (const float*)d_in[0];
    const float* Wa = (const float*)d_in[1];
    const float* Wb = (const float*)d_in[2];
    const float* Wv = (const float*)d_in[3];
    const float* Wp = (const float*)d_in[4];
    const float* bp = (const float*)d_in[5];
    float* out = (float*)d_out;

    float *vbar;
    __half *yh, *xh, *xbar, *ch, *w1, *wv, *wp;
    cudaGetSymbolAddress((void**)&yh,   g_Yh);
    cudaGetSymbolAddress((void**)&vbar, g_VBAR);
    cudaGetSymbolAddress((void**)&xh,   g_Xh);
    cudaGetSymbolAddress((void**)&xbar, g_Xbar);
    cudaGetSymbolAddress((void**)&ch,   g_Ch);
    cudaGetSymbolAddress((void**)&w1,   g_W1);
    cudaGetSymbolAddress((void**)&wv,   g_Wv);
    cudaGetSymbolAddress((void**)&wp,   g_Wp);

    cudaFuncSetAttribute(gemm_fp16<0>,
                         cudaFuncAttributeMaxDynamicSharedMemorySize, GSMEM);
    cudaFuncSetAttribute(gemm_fp16<1>,
                         cudaFuncAttributeMaxDynamicSharedMemorySize, GSMEM);
    cudaFuncSetAttribute(attn_kernel,
                         cudaFuncAttributeMaxDynamicSharedMemorySize, ATTN_SMEM);

    prep_kernel<<<PREP_BLKS, 256>>>(x, Wa, Wb, Wv, Wp, xh, w1, wv, wp, xbar);

    // merged: x@[Wa|Wb] -> Yh fp16 (288 tiles) + xbar@Wv -> VBAR (6 tiles)
    gemm_fp16<0><<<GGRID, GTHR, GSMEM>>>(xh, w1, yh, xbar, wv, vbar, nullptr, 294);

    attn_kernel<<<BATCH * NHEAD * (SEQ / 256), 256, ATTN_SMEM>>>(yh, vbar, ch);

    // ctx @ Wp + bp -> out (192 tiles)
    gemm_fp16<1><<<GGRID, GTHR, GSMEM>>>(ch, wp, out, nullptr, nullptr, nullptr, bp, 192);
}